// round 1
// baseline (speedup 1.0000x reference)
#include <cuda_runtime.h>
#include <cstdint>

#define D_MODEL 512
#define JOINT   640
#define VOCAB   1024
#define BB      4
#define TT      256
#define UU      64
#define M_TOTAL (BB*TT*UU)   // 65536

// ---------------- scratch (no allocations allowed) ----------------
__device__ float g_E[BB*TT*JOINT];        // (1024, 640)
__device__ float g_P[BB*UU*JOINT];        // (256, 640)
__device__ float g_Z[(size_t)M_TOTAL*JOINT]; // (65536, 640) tf32-rounded, 167 MB
__device__ float g_Wt[VOCAB*JOINT];       // tf32-rounded out_w

// ---------------- helpers ----------------
__device__ __forceinline__ float round_tf32(float x) {
    uint32_t u;
    asm("cvt.rna.tf32.f32 %0, %1;" : "=r"(u) : "f"(x));
    return __uint_as_float(u);
}

// accurate tanh independent of fast-math tanhf->MUFU.TANH mapping
__device__ __forceinline__ float tanh_acc(float x) {
    float ax = fabsf(x);
    float ex = expf(-2.0f * ax);          // EX2-based, ~ulp accurate
    float r  = (1.0f - ex) / (1.0f + ex);
    return copysignf(r, x);
}

__device__ __forceinline__ void cp_async16(void* smem_dst, const void* gmem_src) {
    uint32_t s = (uint32_t)__cvta_generic_to_shared(smem_dst);
    asm volatile("cp.async.cg.shared.global [%0], [%1], 16;\n" :: "r"(s), "l"(gmem_src));
}
#define CP_COMMIT() asm volatile("cp.async.commit_group;\n" ::: "memory")
#define CP_WAIT(N)  asm volatile("cp.async.wait_group %0;\n" :: "n"(N) : "memory")

// ---------------- kernel 1: projections  out[m][j] = X[m]·W[j] + bias[j] ----------------
__global__ void proj_kernel(const float* __restrict__ X, const float* __restrict__ W,
                            const float* __restrict__ bias, float* __restrict__ out) {
    __shared__ float sX[16][17];
    __shared__ float sW[16][17];
    int j0 = blockIdx.x * 16, m0 = blockIdx.y * 16;
    int tx = threadIdx.x, ty = threadIdx.y;
    float acc = 0.0f;
    for (int k0 = 0; k0 < D_MODEL; k0 += 16) {
        sX[ty][tx] = X[(m0 + ty) * D_MODEL + k0 + tx];
        sW[ty][tx] = W[(j0 + ty) * D_MODEL + k0 + tx];
        __syncthreads();
#pragma unroll
        for (int k = 0; k < 16; k++) acc += sX[ty][k] * sW[tx][k];
        __syncthreads();
    }
    out[(m0 + ty) * JOINT + j0 + tx] = acc + bias[j0 + tx];
}

// ---------------- kernel 2: Z = tf32(tanh(E + P)) ----------------
__global__ void zjoin_kernel(const float* __restrict__ E, const float* __restrict__ P,
                             float* __restrict__ Z) {
    int idx = blockIdx.x * blockDim.x + threadIdx.x;
    const int JV = JOINT / 4;
    if (idx >= M_TOTAL * JV) return;
    int m = idx / JV;
    int j = (idx - m * JV) * 4;
    int b = m >> 14;            // / (T*U)
    int t = (m >> 6) & (TT - 1);
    int u = m & (UU - 1);
    float4 e = *(const float4*)(E + ((size_t)(b * TT + t)) * JOINT + j);
    float4 p = *(const float4*)(P + ((size_t)(b * UU + u)) * JOINT + j);
    float4 z;
    z.x = round_tf32(tanh_acc(e.x + p.x));
    z.y = round_tf32(tanh_acc(e.y + p.y));
    z.z = round_tf32(tanh_acc(e.z + p.z));
    z.w = round_tf32(tanh_acc(e.w + p.w));
    *(float4*)(Z + (size_t)m * JOINT + j) = z;
}

// ---------------- kernel 3: round out_w ----------------
__global__ void wprep_kernel(const float* __restrict__ W, float* __restrict__ Wt) {
    int idx = blockIdx.x * blockDim.x + threadIdx.x;
    if (idx >= VOCAB * JOINT / 4) return;
    float4 w = *(const float4*)(W + idx * 4);
    w.x = round_tf32(w.x); w.y = round_tf32(w.y);
    w.z = round_tf32(w.z); w.w = round_tf32(w.w);
    *(float4*)(Wt + idx * 4) = w;
}

// ---------------- kernel 4: main GEMM  C(65536x1024) = Z @ Wt^T + out_b ----------------
#define BM 128
#define BN 128
#define BKK 32
#define PAD 36   // floats per smem row: conflict-free frag loads, 144B (16B-mult) stride

__global__ void __launch_bounds__(256) gemm_kernel(
    const float* __restrict__ Z, const float* __restrict__ Wt,
    const float* __restrict__ out_b, float* __restrict__ out) {

    extern __shared__ float smem[];
    const int STAGE = (BM + BN) * PAD;    // floats per stage
    float* sA[2] = { smem,            smem + STAGE };
    float* sB[2] = { smem + BM * PAD, smem + STAGE + BM * PAD };

    const int tid  = threadIdx.x;
    const int lane = tid & 31;
    const int warp = tid >> 5;
    const int wm = warp >> 2;      // 0..1 -> 64-row slab
    const int wn = warp & 3;       // 0..3 -> 32-col slab

    const size_t m_blk = (size_t)blockIdx.y * BM;
    const size_t n_blk = (size_t)blockIdx.x * BN;

    const float* gA0 = Z  + m_blk * JOINT;
    const float* gB0 = Wt + n_blk * JOINT;

    // issue one stage of loads
    auto load_stage = [&](int s, int k0) {
        const float* gA = gA0 + k0;
        const float* gB = gB0 + k0;
#pragma unroll
        for (int i = 0; i < 4; i++) {
            int l = tid + i * 256;          // 0..1023
            int row = l >> 3, c4 = (l & 7) * 4;
            cp_async16(sA[s] + row * PAD + c4, gA + (size_t)row * JOINT + c4);
        }
#pragma unroll
        for (int i = 0; i < 4; i++) {
            int l = tid + i * 256;
            int row = l >> 3, c4 = (l & 7) * 4;
            cp_async16(sB[s] + row * PAD + c4, gB + (size_t)row * JOINT + c4);
        }
        CP_COMMIT();
    };

    float c[4][4][4];
#pragma unroll
    for (int mt = 0; mt < 4; mt++)
#pragma unroll
        for (int nt = 0; nt < 4; nt++)
#pragma unroll
            for (int r = 0; r < 4; r++) c[mt][nt][r] = 0.0f;

    const int NK = JOINT / BKK;   // 20
    load_stage(0, 0);

    for (int kt = 0; kt < NK; kt++) {
        if (kt + 1 < NK) { load_stage((kt + 1) & 1, (kt + 1) * BKK); CP_WAIT(1); }
        else             { CP_WAIT(0); }
        __syncthreads();

        const float* A  = sA[kt & 1];
        const float* Bs = sB[kt & 1];
        const int ar = lane >> 2;
        const int al = lane & 3;

#pragma unroll
        for (int ks = 0; ks < 4; ks++) {
            const int k = ks * 8;
            uint32_t a[4][4], b[4][2];
#pragma unroll
            for (int mt = 0; mt < 4; mt++) {
                int r = wm * 64 + mt * 16 + ar;
                a[mt][0] = __float_as_uint(A[r * PAD + k + al]);
                a[mt][1] = __float_as_uint(A[(r + 8) * PAD + k + al]);
                a[mt][2] = __float_as_uint(A[r * PAD + k + 4 + al]);
                a[mt][3] = __float_as_uint(A[(r + 8) * PAD + k + 4 + al]);
            }
#pragma unroll
            for (int nt = 0; nt < 4; nt++) {
                int n = wn * 32 + nt * 8 + ar;
                b[nt][0] = __float_as_uint(Bs[n * PAD + k + al]);
                b[nt][1] = __float_as_uint(Bs[n * PAD + k + 4 + al]);
            }
#pragma unroll
            for (int mt = 0; mt < 4; mt++)
#pragma unroll
                for (int nt = 0; nt < 4; nt++) {
                    asm volatile(
                        "mma.sync.aligned.m16n8k8.row.col.f32.tf32.tf32.f32 "
                        "{%0,%1,%2,%3}, {%4,%5,%6,%7}, {%8,%9}, {%0,%1,%2,%3};\n"
                        : "+f"(c[mt][nt][0]), "+f"(c[mt][nt][1]),
                          "+f"(c[mt][nt][2]), "+f"(c[mt][nt][3])
                        : "r"(a[mt][0]), "r"(a[mt][1]), "r"(a[mt][2]), "r"(a[mt][3]),
                          "r"(b[nt][0]), "r"(b[nt][1]));
                }
        }
        __syncthreads();
    }

    // epilogue: + out_b, write fp32
    const int m_base = (int)m_blk + wm * 64;
    const int n_base = (int)n_blk + wn * 32;
#pragma unroll
    for (int mt = 0; mt < 4; mt++) {
        int row0 = m_base + mt * 16 + (lane >> 2);
#pragma unroll
        for (int nt = 0; nt < 4; nt++) {
            int col0 = n_base + nt * 8 + 2 * (lane & 3);
            float b0 = out_b[col0], b1 = out_b[col0 + 1];
            float2 v0 = make_float2(c[mt][nt][0] + b0, c[mt][nt][1] + b1);
            float2 v1 = make_float2(c[mt][nt][2] + b0, c[mt][nt][3] + b1);
            *(float2*)(out + (size_t)row0 * VOCAB + col0)       = v0;
            *(float2*)(out + (size_t)(row0 + 8) * VOCAB + col0) = v1;
        }
    }
}

// ---------------- launcher ----------------
extern "C" void kernel_launch(void* const* d_in, const int* in_sizes, int n_in,
                              void* d_out, int out_size) {
    const float* enc    = (const float*)d_in[0];
    const float* pred   = (const float*)d_in[1];
    const float* enc_w  = (const float*)d_in[2];
    const float* enc_b  = (const float*)d_in[3];
    const float* pred_w = (const float*)d_in[4];
    const float* pred_b = (const float*)d_in[5];
    const float* out_w  = (const float*)d_in[6];
    const float* out_b  = (const float*)d_in[7];
    float* out = (float*)d_out;

    float *E, *P, *Z, *Wt;
    cudaGetSymbolAddress((void**)&E,  g_E);
    cudaGetSymbolAddress((void**)&P,  g_P);
    cudaGetSymbolAddress((void**)&Z,  g_Z);
    cudaGetSymbolAddress((void**)&Wt, g_Wt);

    // projections
    {
        dim3 blk(16, 16);
        dim3 grdE(JOINT / 16, (BB * TT) / 16);
        proj_kernel<<<grdE, blk>>>(enc, enc_w, enc_b, E);
        dim3 grdP(JOINT / 16, (BB * UU) / 16);
        proj_kernel<<<grdP, blk>>>(pred, pred_w, pred_b, P);
    }
    // weight prep (independent of projections; same stream ordering is fine)
    {
        int n = VOCAB * JOINT / 4;
        wprep_kernel<<<(n + 255) / 256, 256>>>(out_w, Wt);
    }
    // tanh join
    {
        int n = M_TOTAL * (JOINT / 4);
        zjoin_kernel<<<(n + 255) / 256, 256>>>(E, P, Z);
    }
    // main GEMM
    {
        const int smem_bytes = 2 * (BM + BN) * PAD * (int)sizeof(float); // 73728
        static bool attr_set = false;
        // setting the attribute is idempotent and not a stream op; do it every call
        cudaFuncSetAttribute(gemm_kernel, cudaFuncAttributeMaxDynamicSharedMemorySize,
                             smem_bytes);
        (void)attr_set;
        dim3 grd(VOCAB / BN, M_TOTAL / BM);
        gemm_kernel<<<grd, 256, smem_bytes>>>(Z, Wt, out_b, out);
    }
}

// round 5
// speedup vs baseline: 1.3309x; 1.3309x over previous
#include <cuda_runtime.h>
#include <cstdint>

#define D_MODEL 512
#define JOINT   640
#define VOCAB   1024
#define BB      4
#define TT      256
#define UU      64
#define M_TOTAL (BB*TT*UU)   // 65536

#define BM 64
#define BN 256
#define BK 32
#define NK (JOINT/BK)        // 20

// ---------------- scratch (no allocations allowed) ----------------
__device__ float g_E[BB*TT*JOINT];        // (1024, 640) row-major
__device__ float g_P[BB*UU*JOINT];        // (256, 640)  row-major
// Wt: out_w tf32-rounded AND permuted into mma-fragment order:
// index = ((((nblk*NK + kt)*32 + nb)*4 + kb)*32 + lane)*2 + reg
//   nblk = v>>8, nb = (v>>3)&31, ar = v&7 ; lane = ar*4+al
//   kt = j>>5, kb = (j>>3)&3, al = j&3, reg = (j>>2)&1
__device__ float g_Wt[VOCAB*JOINT];

// ---------------- helpers ----------------
__device__ __forceinline__ float round_tf32(float x) {
    uint32_t u;
    asm("cvt.rna.tf32.f32 %0, %1;" : "=r"(u) : "f"(x));
    return __uint_as_float(u);
}
__device__ __forceinline__ float tanh_fast(float x) {
    float y;
    asm("tanh.approx.f32 %0, %1;" : "=f"(y) : "f"(x));
    return y;
}
__device__ __forceinline__ uint32_t smem_u32(const void* p) {
    return (uint32_t)__cvta_generic_to_shared(p);
}
__device__ __forceinline__ void cp_async16(void* smem_dst, const void* gmem_src) {
    asm volatile("cp.async.cg.shared.global [%0], [%1], 16;\n"
                 :: "r"(smem_u32(smem_dst)), "l"(gmem_src));
}
#define CP_COMMIT() asm volatile("cp.async.commit_group;\n" ::: "memory")
#define CP_WAIT0()  asm volatile("cp.async.wait_group 0;\n" ::: "memory")

// ---------------- kernel 1: projections (64x64 tile, 4x4/thread) ----------------
__global__ void __launch_bounds__(256) proj_kernel(
    const float* __restrict__ X, const float* __restrict__ W,
    const float* __restrict__ bias, float* __restrict__ out) {
    __shared__ float sX[16][68];   // [k][m]
    __shared__ float sW[16][68];   // [k][j]
    const int tid = threadIdx.x;
    const int tx = tid & 15, ty = tid >> 4;
    const int m0 = blockIdx.y * 64, j0 = blockIdx.x * 64;
    const int lrow = tid >> 2, lseg = tid & 3;

    float acc[4][4] = {};
    for (int k0 = 0; k0 < D_MODEL; k0 += 16) {
        float4 xv = *(const float4*)(X + (size_t)(m0 + lrow) * D_MODEL + k0 + lseg * 4);
        float4 wv = *(const float4*)(W + (size_t)(j0 + lrow) * D_MODEL + k0 + lseg * 4);
        sX[lseg * 4 + 0][lrow] = xv.x; sX[lseg * 4 + 1][lrow] = xv.y;
        sX[lseg * 4 + 2][lrow] = xv.z; sX[lseg * 4 + 3][lrow] = xv.w;
        sW[lseg * 4 + 0][lrow] = wv.x; sW[lseg * 4 + 1][lrow] = wv.y;
        sW[lseg * 4 + 2][lrow] = wv.z; sW[lseg * 4 + 3][lrow] = wv.w;
        __syncthreads();
#pragma unroll
        for (int k = 0; k < 16; k++) {
            float4 a = *(const float4*)(&sX[k][ty * 4]);
            float4 b = *(const float4*)(&sW[k][tx * 4]);
            float av[4] = { a.x, a.y, a.z, a.w };
            float bv[4] = { b.x, b.y, b.z, b.w };
#pragma unroll
            for (int i = 0; i < 4; i++)
#pragma unroll
                for (int j = 0; j < 4; j++) acc[i][j] += av[i] * bv[j];
        }
        __syncthreads();
    }
    float4 bv = *(const float4*)(bias + j0 + tx * 4);
    float bb[4] = { bv.x, bv.y, bv.z, bv.w };
#pragma unroll
    for (int i = 0; i < 4; i++) {
        float4 o;
        o.x = acc[i][0] + bb[0]; o.y = acc[i][1] + bb[1];
        o.z = acc[i][2] + bb[2]; o.w = acc[i][3] + bb[3];
        *(float4*)(out + (size_t)(m0 + ty * 4 + i) * JOINT + j0 + tx * 4) = o;
    }
}

// ---------------- kernel 2: tf32-round + fragment-permute out_w ----------------
__global__ void wprep_kernel(const float* __restrict__ W, float* __restrict__ Wt) {
    int d2 = blockIdx.x * blockDim.x + threadIdx.x;     // pair index
    if (d2 >= VOCAB * JOINT / 2) return;
    int lane = d2 & 31;
    int t1 = d2 >> 5;
    int kb = t1 & 3;  t1 >>= 2;
    int nb = t1 & 31; t1 >>= 5;
    int kt = t1 % NK;
    int nblk = t1 / NK;
    int v = nblk * 256 + nb * 8 + (lane >> 2);
    int j = kt * 32 + kb * 8 + (lane & 3);
    float w0 = W[(size_t)v * JOINT + j];
    float w1 = W[(size_t)v * JOINT + j + 4];
    float2 o = make_float2(round_tf32(w0), round_tf32(w1));
    *(float2*)(Wt + (size_t)d2 * 2) = o;
}

// ---------------- kernel 3: fused tanh-join + tf32 mma.sync GEMM ----------------
// smem (bytes): A0[0,8K) A1[8K,16K) B0[16K,48K) B1[48K,80K)
// A stage: frag order ((rb*4+kb)*32 + (lane^kb)) slots of 4 floats,
//          slot order [2*s1 + s2] (=> mma a0=r0, a1=r2, a2=r1, a3=r3)
// B stage: frag order ((nb*4+kb)*32 + lane) slots of 2 floats (b0,b1)
#define SM_A0 0
#define SM_A1 8192
#define SM_B0 16384
#define SM_B1 49152
#define SM_TOTAL 81920

__global__ void __launch_bounds__(256, 2) gemm_fused_kernel(
    const float* __restrict__ E, const float* __restrict__ P,
    const float* __restrict__ Wt, const float* __restrict__ out_b,
    float* __restrict__ out) {

    extern __shared__ char smem[];
    float* const aS[2] = { (float*)(smem + SM_A0), (float*)(smem + SM_A1) };
    float* const bS[2] = { (float*)(smem + SM_B0), (float*)(smem + SM_B1) };

    const int tid  = threadIdx.x;
    const int warp = tid >> 5;
    const int lane = tid & 31;
    const int wm = warp >> 2;       // 0..1 : 32-row slab
    const int wn = warp & 3;        // 0..3 : 64-col slab

    const int m_blk = blockIdx.y * BM;
    const int nblk  = blockIdx.x;                 // 0..3 (256-col block)
    const float* wsrc = Wt + (size_t)nblk * NK * 8192;

    // ---- producer mapping: thread -> (row r, k-block kb_p) ----
    const int r    = tid >> 2;      // 0..63
    const int kb_p = tid & 3;       // 0..3
    const int m = m_blk + r;
    const int b = m >> 14;
    const int t = (m >> 6) & (TT - 1);
    const int u = m & (UU - 1);
    const float* gE = E + (size_t)(b * TT + t) * JOINT + kb_p * 8;
    const float* gP = P + (size_t)(b * UU + u) * JOINT + kb_p * 8;
    const int rb_p = r >> 4;
    const int s1_p = (r >> 3) & 1;
    const int rr_p = r & 7;

    // ---- produce A chunk kt into stage buffer ----
    auto produceA = [&](int kt, float* dst) {
        const float* e = gE + kt * BK;
        const float* p = gP + kt * BK;
        float4 e0 = *(const float4*)(e);
        float4 e1 = *(const float4*)(e + 4);
        float4 p0 = *(const float4*)(p);
        float4 p1 = *(const float4*)(p + 4);
        float z[8];
        z[0] = round_tf32(tanh_fast(e0.x + p0.x));
        z[1] = round_tf32(tanh_fast(e0.y + p0.y));
        z[2] = round_tf32(tanh_fast(e0.z + p0.z));
        z[3] = round_tf32(tanh_fast(e0.w + p0.w));
        z[4] = round_tf32(tanh_fast(e1.x + p1.x));
        z[5] = round_tf32(tanh_fast(e1.y + p1.y));
        z[6] = round_tf32(tanh_fast(e1.z + p1.z));
        z[7] = round_tf32(tanh_fast(e1.w + p1.w));
        float* base = dst + (rb_p * 4 + kb_p) * 128;   // 32 slots * 4 floats
#pragma unroll
        for (int al = 0; al < 4; al++) {
            int ln = (rr_p * 4 + al) ^ kb_p;
            *(float2*)(base + ln * 4 + 2 * s1_p) = make_float2(z[al], z[al + 4]);
        }
    };

    // ---- B chunk: one contiguous 32KB cp.async copy ----
    auto loadB = [&](int kt, float* dst) {
        const float* src = wsrc + (size_t)kt * 8192;
#pragma unroll
        for (int i = 0; i < 8; i++) {
            int seg = tid + i * 256;   // 0..2047 16B segments
            cp_async16((char*)dst + seg * 16, src + seg * 4);
        }
        CP_COMMIT();
    };

    float c[2][8][4];
#pragma unroll
    for (int mt = 0; mt < 2; mt++)
#pragma unroll
        for (int nt = 0; nt < 8; nt++)
#pragma unroll
            for (int q = 0; q < 4; q++) c[mt][nt][q] = 0.0f;

    produceA(0, aS[0]);
    loadB(0, bS[0]);

    for (int kt = 0; kt < NK; kt++) {
        const int s = kt & 1;
        CP_WAIT0();          // only group(kt) in flight here
        __syncthreads();     // A[s] STS visible; everyone done with buffers s^1
        if (kt + 1 < NK) loadB(kt + 1, bS[s ^ 1]);

        const float* A  = aS[s];
        const float* Bs = bS[s];
#pragma unroll
        for (int kb = 0; kb < 4; kb++) {
            uint32_t a[2][4];
#pragma unroll
            for (int mt = 0; mt < 2; mt++) {
                int rb = wm * 2 + mt;
                float4 av = *(const float4*)(A + (rb * 4 + kb) * 128 + (lane ^ kb) * 4);
                a[mt][0] = __float_as_uint(av.x);
                a[mt][1] = __float_as_uint(av.y);
                a[mt][2] = __float_as_uint(av.z);
                a[mt][3] = __float_as_uint(av.w);
            }
            uint32_t bf[8][2];
#pragma unroll
            for (int nt = 0; nt < 8; nt++) {
                int nb = wn * 8 + nt;
                float2 bv = *(const float2*)(Bs + ((nb * 4 + kb) * 32 + lane) * 2);
                bf[nt][0] = __float_as_uint(bv.x);
                bf[nt][1] = __float_as_uint(bv.y);
            }
#pragma unroll
            for (int mt = 0; mt < 2; mt++)
#pragma unroll
                for (int nt = 0; nt < 8; nt++) {
                    // storage order [2*s1+s2] => a0=r0, a1=r2, a2=r1, a3=r3
                    asm volatile(
                        "mma.sync.aligned.m16n8k8.row.col.f32.tf32.tf32.f32 "
                        "{%0,%1,%2,%3}, {%4,%5,%6,%7}, {%8,%9}, {%0,%1,%2,%3};\n"
                        : "+f"(c[mt][nt][0]), "+f"(c[mt][nt][1]),
                          "+f"(c[mt][nt][2]), "+f"(c[mt][nt][3])
                        : "r"(a[mt][0]), "r"(a[mt][2]), "r"(a[mt][1]), "r"(a[mt][3]),
                          "r"(bf[nt][0]), "r"(bf[nt][1]));
                }
        }
        if (kt + 1 < NK) produceA(kt + 1, aS[s ^ 1]);
    }

    // ---- epilogue: +bias, fp32 store ----
    const int m_base = m_blk + wm * 32;
    const int n_base = nblk * BN + wn * 64;
#pragma unroll
    for (int mt = 0; mt < 2; mt++) {
        int row0 = m_base + mt * 16 + (lane >> 2);
#pragma unroll
        for (int nt = 0; nt < 8; nt++) {
            int col0 = n_base + nt * 8 + 2 * (lane & 3);
            float b0 = out_b[col0], b1 = out_b[col0 + 1];
            float2 v0 = make_float2(c[mt][nt][0] + b0, c[mt][nt][1] + b1);
            float2 v1 = make_float2(c[mt][nt][2] + b0, c[mt][nt][3] + b1);
            *(float2*)(out + (size_t)row0 * VOCAB + col0)       = v0;
            *(float2*)(out + (size_t)(row0 + 8) * VOCAB + col0) = v1;
        }
    }
}

// ---------------- launcher ----------------
extern "C" void kernel_launch(void* const* d_in, const int* in_sizes, int n_in,
                              void* d_out, int out_size) {
    const float* enc    = (const float*)d_in[0];
    const float* pred   = (const float*)d_in[1];
    const float* enc_w  = (const float*)d_in[2];
    const float* enc_b  = (const float*)d_in[3];
    const float* pred_w = (const float*)d_in[4];
    const float* pred_b = (const float*)d_in[5];
    const float* out_w  = (const float*)d_in[6];
    const float* out_b  = (const float*)d_in[7];
    float* out = (float*)d_out;

    float *E, *P, *Wt;
    cudaGetSymbolAddress((void**)&E,  g_E);
    cudaGetSymbolAddress((void**)&P,  g_P);
    cudaGetSymbolAddress((void**)&Wt, g_Wt);

    // projections
    {
        dim3 grdE(JOINT / 64, (BB * TT) / 64);   // (10, 16)
        proj_kernel<<<grdE, 256>>>(enc, enc_w, enc_b, E);
        dim3 grdP(JOINT / 64, (BB * UU) / 64);   // (10, 4)
        proj_kernel<<<grdP, 256>>>(pred, pred_w, pred_b, P);
    }
    // weight prep: tf32-round + fragment permute
    {
        int n = VOCAB * JOINT / 2;
        wprep_kernel<<<(n + 255) / 256, 256>>>(out_w, Wt);
    }
    // fused tanh-join + GEMM
    {
        cudaFuncSetAttribute(gemm_fused_kernel,
                             cudaFuncAttributeMaxDynamicSharedMemorySize, SM_TOTAL);
        dim3 grd(VOCAB / BN, M_TOTAL / BM);   // (4, 1024)
        gemm_fused_kernel<<<grd, 256, SM_TOTAL>>>(E, P, Wt, out_b, out);
    }
}

// round 7
// speedup vs baseline: 2.0568x; 1.5454x over previous
#include <cuda_runtime.h>
#include <cuda_fp16.h>
#include <cstdint>

#define D_MODEL 512
#define JOINT   640
#define VOCAB   1024
#define BB      4
#define TT      256
#define UU      64
#define M_TOTAL (BB*TT*UU)   // 65536

#define BM 64
#define BN 256
#define BK 32
#define NK (JOINT/BK)        // 20

// ---------------- scratch (no allocations allowed) ----------------
__device__ float  g_E[BB*TT*JOINT];       // (1024, 640) row-major
__device__ float  g_P[BB*UU*JOINT];       // (256, 640)  row-major
// Wt: out_w as fp16, permuted into m16n8k16 B-fragment order:
// slot s (4 halves): lane=s&31; t=s>>5; ks16=t&1; t>>=1; nb=t&31; t>>=5;
//                    kt=t%NK; nblk=t/NK
// col v = nblk*256 + nb*8 + (lane>>2); k = kt*32 + ks16*16 + {2tg,2tg+1,8+2tg,9+2tg}
__device__ __half g_Wt[VOCAB*JOINT];

// ---------------- helpers ----------------
__device__ __forceinline__ float tanh_fast(float x) {
    float y;
    asm("tanh.approx.f32 %0, %1;" : "=f"(y) : "f"(x));
    return y;
}
__device__ __forceinline__ uint32_t smem_u32(const void* p) {
    return (uint32_t)__cvta_generic_to_shared(p);
}
__device__ __forceinline__ void cp_async16(void* smem_dst, const void* gmem_src) {
    asm volatile("cp.async.cg.shared.global [%0], [%1], 16;\n"
                 :: "r"(smem_u32(smem_dst)), "l"(gmem_src));
}
#define CP_COMMIT() asm volatile("cp.async.commit_group;\n" ::: "memory")
#define CP_WAIT0()  asm volatile("cp.async.wait_group 0;\n" ::: "memory")

// ---------------- kernel 1: projections (64x64 tile, 4x4/thread) ----------------
__global__ void __launch_bounds__(256) proj_kernel(
    const float* __restrict__ X, const float* __restrict__ W,
    const float* __restrict__ bias, float* __restrict__ out) {
    __shared__ float sX[16][68];   // [k][m]
    __shared__ float sW[16][68];   // [k][j]
    const int tid = threadIdx.x;
    const int tx = tid & 15, ty = tid >> 4;
    const int m0 = blockIdx.y * 64, j0 = blockIdx.x * 64;
    const int lrow = tid >> 2, lseg = tid & 3;

    float acc[4][4] = {};
    for (int k0 = 0; k0 < D_MODEL; k0 += 16) {
        float4 xv = *(const float4*)(X + (size_t)(m0 + lrow) * D_MODEL + k0 + lseg * 4);
        float4 wv = *(const float4*)(W + (size_t)(j0 + lrow) * D_MODEL + k0 + lseg * 4);
        sX[lseg * 4 + 0][lrow] = xv.x; sX[lseg * 4 + 1][lrow] = xv.y;
        sX[lseg * 4 + 2][lrow] = xv.z; sX[lseg * 4 + 3][lrow] = xv.w;
        sW[lseg * 4 + 0][lrow] = wv.x; sW[lseg * 4 + 1][lrow] = wv.y;
        sW[lseg * 4 + 2][lrow] = wv.z; sW[lseg * 4 + 3][lrow] = wv.w;
        __syncthreads();
#pragma unroll
        for (int k = 0; k < 16; k++) {
            float4 a = *(const float4*)(&sX[k][ty * 4]);
            float4 b = *(const float4*)(&sW[k][tx * 4]);
            float av[4] = { a.x, a.y, a.z, a.w };
            float bv[4] = { b.x, b.y, b.z, b.w };
#pragma unroll
            for (int i = 0; i < 4; i++)
#pragma unroll
                for (int j = 0; j < 4; j++) acc[i][j] += av[i] * bv[j];
        }
        __syncthreads();
    }
    float4 bv = *(const float4*)(bias + j0 + tx * 4);
    float bb[4] = { bv.x, bv.y, bv.z, bv.w };
#pragma unroll
    for (int i = 0; i < 4; i++) {
        float4 o;
        o.x = acc[i][0] + bb[0]; o.y = acc[i][1] + bb[1];
        o.z = acc[i][2] + bb[2]; o.w = acc[i][3] + bb[3];
        *(float4*)(out + (size_t)(m0 + ty * 4 + i) * JOINT + j0 + tx * 4) = o;
    }
}

// ---------------- kernel 2: fp16-convert + fragment-permute out_w ----------------
__global__ void wprep_kernel(const float* __restrict__ W, __half* __restrict__ Wt) {
    int s = blockIdx.x * blockDim.x + threadIdx.x;    // slot index (4 halves each)
    if (s >= VOCAB * JOINT / 4) return;
    int lane = s & 31;
    int t1 = s >> 5;
    int ks16 = t1 & 1;  t1 >>= 1;
    int nb   = t1 & 31; t1 >>= 5;
    int kt   = t1 % NK;
    int nblk = t1 / NK;
    int tg = lane & 3;
    int v  = nblk * 256 + nb * 8 + (lane >> 2);
    int kb = kt * 32 + ks16 * 16 + 2 * tg;
    const float* wr = W + (size_t)v * JOINT;
    float2 w0 = *(const float2*)(wr + kb);        // k = kb, kb+1   -> b0
    float2 w1 = *(const float2*)(wr + kb + 8);    // k = kb+8, kb+9 -> b1
    __half2 h0 = __floats2half2_rn(w0.x, w0.y);
    __half2 h1 = __floats2half2_rn(w1.x, w1.y);
    uint2 o;
    o.x = *(const uint32_t*)&h0;
    o.y = *(const uint32_t*)&h1;
    *(uint2*)(Wt + (size_t)s * 4) = o;
}

// ---------------- kernel 3: fused tanh-join + fp16 mma.sync GEMM ----------------
// smem (bytes): A0[0,4K) A1[4K,8K) B0[8K,24K) B1[24K,40K)
// A stage: slot ((rb*2+ks16)*32 + lane) of 16B = {a0,a1,a2,a3} (f16x2 each)
// B stage: slot ((nb*2+ks16)*32 + lane) of 8B  = {b0,b1}
#define SM_A0 0
#define SM_A1 4096
#define SM_B0 8192
#define SM_B1 24576
#define SM_TOTAL 40960

__global__ void __launch_bounds__(256, 2) gemm_fused_kernel(
    const float* __restrict__ E, const float* __restrict__ P,
    const __half* __restrict__ Wt, const float* __restrict__ out_b,
    float* __restrict__ out) {

    extern __shared__ char smem[];
    uint32_t* const aS[2] = { (uint32_t*)(smem + SM_A0), (uint32_t*)(smem + SM_A1) };
    uint32_t* const bS[2] = { (uint32_t*)(smem + SM_B0), (uint32_t*)(smem + SM_B1) };

    const int tid  = threadIdx.x;
    const int warp = tid >> 5;
    const int lane = tid & 31;
    const int wm = warp >> 2;       // 0..1 : 32-row slab
    const int wn = warp & 3;        // 0..3 : 64-col slab

    const int m_blk = blockIdx.y * BM;
    const int nblk  = blockIdx.x;                 // 0..3 (256-col block)
    const __half* wsrc = Wt + (size_t)nblk * NK * 8192;

    // ---- producer mapping: thread -> (row r, quarter q) ----
    const int r = tid >> 2;        // 0..63
    const int q = tid & 3;         // 0..3 : 8 k-values each
    const int m = m_blk + r;
    const int b = m >> 14;
    const int t = (m >> 6) & (TT - 1);
    const int u = m & (UU - 1);
    const float* gE = E + (size_t)(b * TT + t) * JOINT + q * 8;
    const float* gP = P + (size_t)(b * UU + u) * JOINT + q * 8;
    const int rb_p   = r >> 4;          // 16-row block
    const int g_p    = r & 7;           // groupID within block
    const int hi_p   = (r >> 3) & 1;    // 0: a0/a2, 1: a1/a3
    const int ks16_p = q >> 1;
    const int reg_p  = hi_p + 2 * (q & 1);
    // base slot for this thread's 4 target lanes
    uint32_t* const aDst[2] = {
        aS[0] + ((rb_p * 2 + ks16_p) * 32 + g_p * 4) * 4 + reg_p,
        aS[1] + ((rb_p * 2 + ks16_p) * 32 + g_p * 4) * 4 + reg_p };

    // ---- produce A chunk kt into stage buffer s ----
    auto produceA = [&](int kt, int s) {
        const float* e = gE + kt * BK;
        const float* p = gP + kt * BK;
        float4 e0 = *(const float4*)(e);
        float4 e1 = *(const float4*)(e + 4);
        float4 p0 = *(const float4*)(p);
        float4 p1 = *(const float4*)(p + 4);
        __half2 h[4];
        h[0] = __floats2half2_rn(tanh_fast(e0.x + p0.x), tanh_fast(e0.y + p0.y));
        h[1] = __floats2half2_rn(tanh_fast(e0.z + p0.z), tanh_fast(e0.w + p0.w));
        h[2] = __floats2half2_rn(tanh_fast(e1.x + p1.x), tanh_fast(e1.y + p1.y));
        h[3] = __floats2half2_rn(tanh_fast(e1.z + p1.z), tanh_fast(e1.w + p1.w));
        uint32_t* base = aDst[s];
#pragma unroll
        for (int tg = 0; tg < 4; tg++)
            base[tg * 4] = *(const uint32_t*)&h[tg];
    };

    // ---- B chunk: one contiguous 16KB cp.async copy ----
    auto loadB = [&](int kt, int s) {
        const __half* src = wsrc + (size_t)kt * 8192;
        char* dst = (char*)bS[s];
#pragma unroll
        for (int i = 0; i < 4; i++) {
            int seg = tid + i * 256;   // 0..1023 16B segments
            cp_async16(dst + seg * 16, src + seg * 8);
        }
        CP_COMMIT();
    };

    float c[2][8][4];
#pragma unroll
    for (int mt = 0; mt < 2; mt++)
#pragma unroll
        for (int nt = 0; nt < 8; nt++)
#pragma unroll
            for (int qq = 0; qq < 4; qq++) c[mt][nt][qq] = 0.0f;

    produceA(0, 0);
    loadB(0, 0);

    for (int kt = 0; kt < NK; kt++) {
        const int s = kt & 1;
        CP_WAIT0();          // only group(kt) in flight here
        __syncthreads();     // A[s] STS visible; all warps done with buffers s^1
        if (kt + 1 < NK) loadB(kt + 1, s ^ 1);

        const uint32_t* A  = aS[s];
        const uint32_t* Bs = bS[s];
#pragma unroll
        for (int ks = 0; ks < 2; ks++) {
            uint32_t a[2][4];
#pragma unroll
            for (int mt = 0; mt < 2; mt++) {
                int rb = wm * 2 + mt;
                uint4 av = *(const uint4*)(A + ((rb * 2 + ks) * 32 + lane) * 4);
                a[mt][0] = av.x; a[mt][1] = av.y; a[mt][2] = av.z; a[mt][3] = av.w;
            }
            uint32_t bf[8][2];
#pragma unroll
            for (int nt = 0; nt < 8; nt++) {
                int nb = wn * 8 + nt;
                uint2 bv = *(const uint2*)(Bs + ((nb * 2 + ks) * 32 + lane) * 2);
                bf[nt][0] = bv.x; bf[nt][1] = bv.y;
            }
#pragma unroll
            for (int mt = 0; mt < 2; mt++)
#pragma unroll
                for (int nt = 0; nt < 8; nt++) {
                    asm volatile(
                        "mma.sync.aligned.m16n8k16.row.col.f32.f16.f16.f32 "
                        "{%0,%1,%2,%3}, {%4,%5,%6,%7}, {%8,%9}, {%0,%1,%2,%3};\n"
                        : "+f"(c[mt][nt][0]), "+f"(c[mt][nt][1]),
                          "+f"(c[mt][nt][2]), "+f"(c[mt][nt][3])
                        : "r"(a[mt][0]), "r"(a[mt][1]), "r"(a[mt][2]), "r"(a[mt][3]),
                          "r"(bf[nt][0]), "r"(bf[nt][1]));
                }
        }
        if (kt + 1 < NK) produceA(kt + 1, s ^ 1);
    }

    // ---- epilogue: +bias, fp32 store ----
    const int m_base = m_blk + wm * 32;
    const int n_base = nblk * BN + wn * 64;
#pragma unroll
    for (int mt = 0; mt < 2; mt++) {
        int row0 = m_base + mt * 16 + (lane >> 2);
#pragma unroll
        for (int nt = 0; nt < 8; nt++) {
            int col0 = n_base + nt * 8 + 2 * (lane & 3);
            float b0 = out_b[col0], b1 = out_b[col0 + 1];
            float2 v0 = make_float2(c[mt][nt][0] + b0, c[mt][nt][1] + b1);
            float2 v1 = make_float2(c[mt][nt][2] + b0, c[mt][nt][3] + b1);
            *(float2*)(out + (size_t)row0 * VOCAB + col0)       = v0;
            *(float2*)(out + (size_t)(row0 + 8) * VOCAB + col0) = v1;
        }
    }
}

// ---------------- launcher ----------------
extern "C" void kernel_launch(void* const* d_in, const int* in_sizes, int n_in,
                              void* d_out, int out_size) {
    const float* enc    = (const float*)d_in[0];
    const float* pred   = (const float*)d_in[1];
    const float* enc_w  = (const float*)d_in[2];
    const float* enc_b  = (const float*)d_in[3];
    const float* pred_w = (const float*)d_in[4];
    const float* pred_b = (const float*)d_in[5];
    const float* out_w  = (const float*)d_in[6];
    const float* out_b  = (const float*)d_in[7];
    float* out = (float*)d_out;

    float *E, *P;
    __half* Wt;
    cudaGetSymbolAddress((void**)&E,  g_E);
    cudaGetSymbolAddress((void**)&P,  g_P);
    cudaGetSymbolAddress((void**)&Wt, g_Wt);

    // projections
    {
        dim3 grdE(JOINT / 64, (BB * TT) / 64);   // (10, 16)
        proj_kernel<<<grdE, 256>>>(enc, enc_w, enc_b, E);
        dim3 grdP(JOINT / 64, (BB * UU) / 64);   // (10, 4)
        proj_kernel<<<grdP, 256>>>(pred, pred_w, pred_b, P);
    }
    // weight prep: fp16 convert + fragment permute
    {
        int n = VOCAB * JOINT / 4;
        wprep_kernel<<<(n + 255) / 256, 256>>>(out_w, Wt);
    }
    // fused tanh-join + GEMM
    {
        cudaFuncSetAttribute(gemm_fused_kernel,
                             cudaFuncAttributeMaxDynamicSharedMemorySize, SM_TOTAL);
        dim3 grd(VOCAB / BN, M_TOTAL / BM);   // (4, 1024)
        gemm_fused_kernel<<<grd, 256, SM_TOTAL>>>(E, P, Wt, out_b, out);
    }
}

// round 9
// speedup vs baseline: 2.3956x; 1.1647x over previous
#include <cuda_runtime.h>
#include <cuda_fp16.h>
#include <cstdint>

#define D_MODEL 512
#define JOINT   640
#define VOCAB   1024
#define BB      4
#define TT      256
#define UU      64
#define M_TOTAL (BB*TT*UU)   // 65536

#define BM 64
#define BN 256
#define BK 32
#define NK (JOINT/BK)        // 20

// ---------------- scratch (no allocations allowed) ----------------
__device__ float  g_E[BB*TT*JOINT];       // (1024, 640) row-major
__device__ float  g_P[BB*UU*JOINT];       // (256, 640)  row-major
// Wt: fp16 out_w in m16n8k16 B-fragment order, 16B slot s:
//   lane=s&31; t=s>>5; ks=t&1; t>>=1; nbp=t&15; t>>=4; kt=t%NK; nblk=t/NK
//   g=lane>>2; tg=lane&3; v=nblk*256+nbp*16+g; k=kt*32+ks*16+2tg
//   slot = { (v,k|k+1), (v,k+8|k+9), (v+8,k|k+1), (v+8,k+8|k+9) } as half2s
__device__ __half g_Wt[VOCAB*JOINT];

// ---------------- helpers ----------------
__device__ __forceinline__ float tanh_fast(float x) {
    float y;
    asm("tanh.approx.f32 %0, %1;" : "=f"(y) : "f"(x));
    return y;
}
__device__ __forceinline__ uint32_t smem_u32(const void* p) {
    return (uint32_t)__cvta_generic_to_shared(p);
}
__device__ __forceinline__ void cp_async16(void* smem_dst, const void* gmem_src) {
    asm volatile("cp.async.cg.shared.global [%0], [%1], 16;\n"
                 :: "r"(smem_u32(smem_dst)), "l"(gmem_src));
}
#define CP_COMMIT() asm volatile("cp.async.commit_group;\n" ::: "memory")
#define CP_WAIT0()  asm volatile("cp.async.wait_group 0;\n" ::: "memory")

// ---------------- projection tile (device fn): out[m][j] = X[m]·W[j] + b[j] ----
__device__ void proj_tile(const float* __restrict__ X, const float* __restrict__ W,
                          const float* __restrict__ bias, float* __restrict__ out,
                          int m0, int j0) {
    __shared__ float sX[16][68];   // [k][m]
    __shared__ float sW[16][68];   // [k][j]
    const int tid = threadIdx.x;
    const int tx = tid & 15, ty = tid >> 4;
    const int lrow = tid >> 2, lseg = tid & 3;

    float acc[4][4] = {};
    for (int k0 = 0; k0 < D_MODEL; k0 += 16) {
        float4 xv = *(const float4*)(X + (size_t)(m0 + lrow) * D_MODEL + k0 + lseg * 4);
        float4 wv = *(const float4*)(W + (size_t)(j0 + lrow) * D_MODEL + k0 + lseg * 4);
        sX[lseg * 4 + 0][lrow] = xv.x; sX[lseg * 4 + 1][lrow] = xv.y;
        sX[lseg * 4 + 2][lrow] = xv.z; sX[lseg * 4 + 3][lrow] = xv.w;
        sW[lseg * 4 + 0][lrow] = wv.x; sW[lseg * 4 + 1][lrow] = wv.y;
        sW[lseg * 4 + 2][lrow] = wv.z; sW[lseg * 4 + 3][lrow] = wv.w;
        __syncthreads();
#pragma unroll
        for (int k = 0; k < 16; k++) {
            float4 a = *(const float4*)(&sX[k][ty * 4]);
            float4 b = *(const float4*)(&sW[k][tx * 4]);
            float av[4] = { a.x, a.y, a.z, a.w };
            float bv[4] = { b.x, b.y, b.z, b.w };
#pragma unroll
            for (int i = 0; i < 4; i++)
#pragma unroll
                for (int j = 0; j < 4; j++) acc[i][j] += av[i] * bv[j];
        }
        __syncthreads();
    }
    float4 bv = *(const float4*)(bias + j0 + tx * 4);
    float bb[4] = { bv.x, bv.y, bv.z, bv.w };
#pragma unroll
    for (int i = 0; i < 4; i++) {
        float4 o;
        o.x = acc[i][0] + bb[0]; o.y = acc[i][1] + bb[1];
        o.z = acc[i][2] + bb[2]; o.w = acc[i][3] + bb[3];
        *(float4*)(out + (size_t)(m0 + ty * 4 + i) * JOINT + j0 + tx * 4) = o;
    }
}

// ---------------- kernel 1: fused prep (wprep + E-proj + P-proj) ----------------
// bid [0,320): wprep  [320,480): E proj 64x64 tiles  [480,520): P proj
__global__ void __launch_bounds__(256) prep_kernel(
    const float* __restrict__ enc,    const float* __restrict__ pred,
    const float* __restrict__ enc_w,  const float* __restrict__ enc_b,
    const float* __restrict__ pred_w, const float* __restrict__ pred_b,
    const float* __restrict__ out_w,
    float* __restrict__ E, float* __restrict__ Pq, __half* __restrict__ Wt) {
    const int bid = blockIdx.x;
    if (bid < 320) {
        int s = bid * 256 + threadIdx.x;          // 16B-slot index, 81920 total
        int lane = s & 31;
        int t1 = s >> 5;
        int ks  = t1 & 1;  t1 >>= 1;
        int nbp = t1 & 15; t1 >>= 4;
        int kt  = t1 % NK;
        int nblk = t1 / NK;
        int g = lane >> 2, tg = lane & 3;
        int v = nblk * 256 + nbp * 16 + g;
        int k = kt * 32 + ks * 16 + 2 * tg;
        const float* w0 = out_w + (size_t)v * JOINT;
        const float* w1 = w0 + (size_t)8 * JOINT;
        float2 aa = *(const float2*)(w0 + k);
        float2 ab = *(const float2*)(w0 + k + 8);
        float2 ba = *(const float2*)(w1 + k);
        float2 bb = *(const float2*)(w1 + k + 8);
        __half2 h0 = __floats2half2_rn(aa.x, aa.y);
        __half2 h1 = __floats2half2_rn(ab.x, ab.y);
        __half2 h2 = __floats2half2_rn(ba.x, ba.y);
        __half2 h3 = __floats2half2_rn(bb.x, bb.y);
        uint4 o;
        o.x = *(const uint32_t*)&h0; o.y = *(const uint32_t*)&h1;
        o.z = *(const uint32_t*)&h2; o.w = *(const uint32_t*)&h3;
        *(uint4*)(Wt + (size_t)s * 8) = o;
    } else if (bid < 480) {
        int idx = bid - 320;                      // 160 tiles: 16 m x 10 j
        proj_tile(enc, enc_w, enc_b, E, (idx / 10) * 64, (idx % 10) * 64);
    } else {
        int idx = bid - 480;                      // 40 tiles: 4 m x 10 j
        proj_tile(pred, pred_w, pred_b, Pq, (idx / 10) * 64, (idx % 10) * 64);
    }
}

// ---------------- kernel 2: fused tanh-join + fp16 mma.sync GEMM ----------------
// smem: A0[0,4K) A1[4K,8K) B0[8K,24K) B1[24K,40K)
// A stage: slot ((rb*2+ks)*32+lane) 16B = {a0,a1,a2,a3}
// B stage: slot ((nbp*2+ks)*32+lane) 16B = {nb_even b0,b1, nb_odd b0,b1}
#define SM_A0 0
#define SM_A1 4096
#define SM_B0 8192
#define SM_B1 24576
#define SM_TOTAL 40960

__global__ void __launch_bounds__(256, 2) gemm_fused_kernel(
    const float* __restrict__ E, const float* __restrict__ P,
    const __half* __restrict__ Wt, const float* __restrict__ out_b,
    float* __restrict__ out) {

    extern __shared__ char smem[];
    uint32_t* const aS[2] = { (uint32_t*)(smem + SM_A0), (uint32_t*)(smem + SM_A1) };
    uint32_t* const bS[2] = { (uint32_t*)(smem + SM_B0), (uint32_t*)(smem + SM_B1) };

    const int tid  = threadIdx.x;
    const int warp = tid >> 5;
    const int lane = tid & 31;
    const int wm = warp >> 2;       // 0..1 : 32-row slab
    const int wn = warp & 3;        // 0..3 : 64-col slab

    const int bt    = blockIdx.y;                 // = b*T + t  (0..1023)
    const int m_blk = bt * BM;
    const int nblk  = blockIdx.x;                 // 0..3 (256-col block)
    const __half* wsrc = Wt + (size_t)nblk * NK * 8192;

    // ---- producer mapping: thread tid <-> A fragment slot tid ----
    // blk = tid>>5 = rb*2+ks ; lane: g = >>2, tg = &3
    const int blk_p = tid >> 5;
    const int rb_p  = blk_p >> 1;
    const int ks_p  = blk_p & 1;
    const int g_p   = (tid >> 2) & 7;
    const int tg_p  = tid & 3;
    const int kk_p  = ks_p * 16 + 2 * tg_p;       // k offset within chunk
    const int u0    = rb_p * 16 + g_p;            // P row (u); u1 = u0+8
    const int b_    = bt >> 8;                    // batch
    const float* gEk = E + (size_t)bt * JOINT + kk_p;                 // broadcast row
    const float* gP0 = P + (size_t)(b_ * UU + u0) * JOINT + kk_p;
    const float* gP1 = gP0 + (size_t)8 * JOINT;

    // ---- B chunk: one contiguous 16KB cp.async copy ----
    auto loadB = [&](int kt, int s) {
        const __half* src = wsrc + (size_t)kt * 8192;
        char* dst = (char*)bS[s];
#pragma unroll
        for (int i = 0; i < 4; i++) {
            int seg = tid + i * 256;
            cp_async16(dst + seg * 16, src + seg * 8);
        }
        CP_COMMIT();
    };

    // ---- produce A chunk 0 (prologue) ----
    {
        float2 eA  = *(const float2*)(gEk);
        float2 eB  = *(const float2*)(gEk + 8);
        float2 p0A = *(const float2*)(gP0);
        float2 p0B = *(const float2*)(gP0 + 8);
        float2 p1A = *(const float2*)(gP1);
        float2 p1B = *(const float2*)(gP1 + 8);
        __half2 a0 = __floats2half2_rn(tanh_fast(eA.x + p0A.x), tanh_fast(eA.y + p0A.y));
        __half2 a1 = __floats2half2_rn(tanh_fast(eA.x + p1A.x), tanh_fast(eA.y + p1A.y));
        __half2 a2 = __floats2half2_rn(tanh_fast(eB.x + p0B.x), tanh_fast(eB.y + p0B.y));
        __half2 a3 = __floats2half2_rn(tanh_fast(eB.x + p1B.x), tanh_fast(eB.y + p1B.y));
        uint4 st;
        st.x = *(const uint32_t*)&a0; st.y = *(const uint32_t*)&a1;
        st.z = *(const uint32_t*)&a2; st.w = *(const uint32_t*)&a3;
        *(uint4*)(aS[0] + tid * 4) = st;
    }
    loadB(0, 0);

    float c[2][8][4];
#pragma unroll
    for (int mt = 0; mt < 2; mt++)
#pragma unroll
        for (int nt = 0; nt < 8; nt++)
#pragma unroll
            for (int qq = 0; qq < 4; qq++) c[mt][nt][qq] = 0.0f;

    for (int kt = 0; kt < NK; kt++) {
        const int s = kt & 1;
        CP_WAIT0();
        __syncthreads();
        const bool more = (kt + 1 < NK);
        if (more) loadB(kt + 1, s ^ 1);

        // early LDG for next A chunk (latency hidden under ks0 MMAs)
        float2 eA, eB, p0A, p0B, p1A, p1B;
        if (more) {
            const int ko = (kt + 1) * BK;
            eA  = *(const float2*)(gEk + ko);
            eB  = *(const float2*)(gEk + ko + 8);
            p0A = *(const float2*)(gP0 + ko);
            p0B = *(const float2*)(gP0 + ko + 8);
            p1A = *(const float2*)(gP1 + ko);
            p1B = *(const float2*)(gP1 + ko + 8);
        }

        const uint32_t* A  = aS[s];
        const uint32_t* Bs = bS[s];

        // ---------- ks = 0 ----------
        {
            uint32_t a[2][4];
#pragma unroll
            for (int mt = 0; mt < 2; mt++) {
                int rb = wm * 2 + mt;
                uint4 av = *(const uint4*)(A + ((rb * 2 + 0) * 32 + lane) * 4);
                a[mt][0] = av.x; a[mt][1] = av.y; a[mt][2] = av.z; a[mt][3] = av.w;
            }
            uint32_t bf[8][2];
#pragma unroll
            for (int np = 0; np < 4; np++) {
                uint4 bv = *(const uint4*)(Bs + (((wn * 4 + np) * 2 + 0) * 32 + lane) * 4);
                bf[2 * np][0] = bv.x;     bf[2 * np][1] = bv.y;
                bf[2 * np + 1][0] = bv.z; bf[2 * np + 1][1] = bv.w;
            }
#pragma unroll
            for (int mt = 0; mt < 2; mt++)
#pragma unroll
                for (int nt = 0; nt < 8; nt++) {
                    asm volatile(
                        "mma.sync.aligned.m16n8k16.row.col.f32.f16.f16.f32 "
                        "{%0,%1,%2,%3}, {%4,%5,%6,%7}, {%8,%9}, {%0,%1,%2,%3};\n"
                        : "+f"(c[mt][nt][0]), "+f"(c[mt][nt][1]),
                          "+f"(c[mt][nt][2]), "+f"(c[mt][nt][3])
                        : "r"(a[mt][0]), "r"(a[mt][1]), "r"(a[mt][2]), "r"(a[mt][3]),
                          "r"(bf[nt][0]), "r"(bf[nt][1]));
                }
        }

        // ---------- tanh + STS for chunk kt+1 (mid-chunk, overlaps pipes) ----------
        if (more) {
            __half2 a0 = __floats2half2_rn(tanh_fast(eA.x + p0A.x), tanh_fast(eA.y + p0A.y));
            __half2 a1 = __floats2half2_rn(tanh_fast(eA.x + p1A.x), tanh_fast(eA.y + p1A.y));
            __half2 a2 = __floats2half2_rn(tanh_fast(eB.x + p0B.x), tanh_fast(eB.y + p0B.y));
            __half2 a3 = __floats2half2_rn(tanh_fast(eB.x + p1B.x), tanh_fast(eB.y + p1B.y));
            uint4 st;
            st.x = *(const uint32_t*)&a0; st.y = *(const uint32_t*)&a1;
            st.z = *(const uint32_t*)&a2; st.w = *(const uint32_t*)&a3;
            *(uint4*)(aS[s ^ 1] + tid * 4) = st;
        }

        // ---------- ks = 1 ----------
        {
            uint32_t a[2][4];
#pragma unroll
            for (int mt = 0; mt < 2; mt++) {
                int rb = wm * 2 + mt;
                uint4 av = *(const uint4*)(A + ((rb * 2 + 1) * 32 + lane) * 4);
                a[mt][0] = av.x; a[mt][1] = av.y; a[mt][2] = av.z; a[mt][3] = av.w;
            }
            uint32_t bf[8][2];
#pragma unroll
            for (int np = 0; np < 4; np++) {
                uint4 bv = *(const uint4*)(Bs + (((wn * 4 + np) * 2 + 1) * 32 + lane) * 4);
                bf[2 * np][0] = bv.x;     bf[2 * np][1] = bv.y;
                bf[2 * np + 1][0] = bv.z; bf[2 * np + 1][1] = bv.w;
            }
#pragma unroll
            for (int mt = 0; mt < 2; mt++)
#pragma unroll
                for (int nt = 0; nt < 8; nt++) {
                    asm volatile(
                        "mma.sync.aligned.m16n8k16.row.col.f32.f16.f16.f32 "
                        "{%0,%1,%2,%3}, {%4,%5,%6,%7}, {%8,%9}, {%0,%1,%2,%3};\n"
                        : "+f"(c[mt][nt][0]), "+f"(c[mt][nt][1]),
                          "+f"(c[mt][nt][2]), "+f"(c[mt][nt][3])
                        : "r"(a[mt][0]), "r"(a[mt][1]), "r"(a[mt][2]), "r"(a[mt][3]),
                          "r"(bf[nt][0]), "r"(bf[nt][1]));
                }
        }
    }

    // ---- epilogue: +bias, fp32 store ----
    const int m_base = m_blk + wm * 32;
    const int n_base = nblk * BN + wn * 64;
#pragma unroll
    for (int mt = 0; mt < 2; mt++) {
        int row0 = m_base + mt * 16 + (lane >> 2);
#pragma unroll
        for (int nt = 0; nt < 8; nt++) {
            int col0 = n_base + nt * 8 + 2 * (lane & 3);
            float b0 = out_b[col0], b1 = out_b[col0 + 1];
            float2 v0 = make_float2(c[mt][nt][0] + b0, c[mt][nt][1] + b1);
            float2 v1 = make_float2(c[mt][nt][2] + b0, c[mt][nt][3] + b1);
            *(float2*)(out + (size_t)row0 * VOCAB + col0)       = v0;
            *(float2*)(out + (size_t)(row0 + 8) * VOCAB + col0) = v1;
        }
    }
}

// ---------------- launcher ----------------
extern "C" void kernel_launch(void* const* d_in, const int* in_sizes, int n_in,
                              void* d_out, int out_size) {
    const float* enc    = (const float*)d_in[0];
    const float* pred   = (const float*)d_in[1];
    const float* enc_w  = (const float*)d_in[2];
    const float* enc_b  = (const float*)d_in[3];
    const float* pred_w = (const float*)d_in[4];
    const float* pred_b = (const float*)d_in[5];
    const float* out_w  = (const float*)d_in[6];
    const float* out_b  = (const float*)d_in[7];
    float* out = (float*)d_out;

    float *E, *P;
    __half* Wt;
    cudaGetSymbolAddress((void**)&E,  g_E);
    cudaGetSymbolAddress((void**)&P,  g_P);
    cudaGetSymbolAddress((void**)&Wt, g_Wt);

    // fused prep: wprep (320) + E proj (160) + P proj (40)
    prep_kernel<<<520, 256>>>(enc, pred, enc_w, enc_b, pred_w, pred_b, out_w,
                              E, P, Wt);

    // fused tanh-join + GEMM
    cudaFuncSetAttribute(gemm_fused_kernel,
                         cudaFuncAttributeMaxDynamicSharedMemorySize, SM_TOTAL);
    dim3 grd(VOCAB / BN, M_TOTAL / BM);   // (4, 1024)
    gemm_fused_kernel<<<grd, 256, SM_TOTAL>>>(E, P, Wt, out_b, out);
}

// round 10
// speedup vs baseline: 2.6608x; 1.1107x over previous
#include <cuda_runtime.h>
#include <cuda_fp16.h>
#include <cstdint>

#define D_MODEL 512
#define JOINT   640
#define VOCAB   1024
#define BB      4
#define TT      256
#define UU      64
#define M_TOTAL (BB*TT*UU)   // 65536

#define BM 64
#define BN 256
#define BK 32
#define NK (JOINT/BK)        // 20

// ---------------- scratch (no allocations allowed) ----------------
// E_perm: per (bt,kt,ks,tg): float4 {E[bt][k0],E[k0+1],E[k0+8],E[k0+9]},
//         k0 = kt*32+ks*16+2tg ; addr = bt*640 + kt*32 + (ks*4+tg)*4 floats
__device__ float  g_E[BB*TT*JOINT];
// P_perm: slot idx = part*256 + ptid (ptid = producer tid), per (b,kt):
//         float4 {P[b][u][k0],+1,+8,+9}, u = rb*16+g+part*8, k0 = kt*32+ks*16+2tg
//         (blk=ptid>>5, rb=blk>>1, ks=blk&1, g=(ptid>>2)&7, tg=ptid&3)
//         addr = ((b*NK+kt)*512 + idx)*4 floats
__device__ float  g_P[BB*UU*JOINT];
// Wt: fp16 out_w in m16n8k16 paired-B fragment order (same as round 9)
__device__ __half g_Wt[VOCAB*JOINT];

// ---------------- helpers ----------------
__device__ __forceinline__ float tanh_fast(float x) {
    float y;
    asm("tanh.approx.f32 %0, %1;" : "=f"(y) : "f"(x));
    return y;
}
__device__ __forceinline__ uint32_t smem_u32(const void* p) {
    return (uint32_t)__cvta_generic_to_shared(p);
}
__device__ __forceinline__ void cp_async16(void* smem_dst, const void* gmem_src) {
    asm volatile("cp.async.cg.shared.global [%0], [%1], 16;\n"
                 :: "r"(smem_u32(smem_dst)), "l"(gmem_src));
}
#define CP_COMMIT() asm volatile("cp.async.commit_group;\n" ::: "memory")
#define CP_WAIT0()  asm volatile("cp.async.wait_group 0;\n" ::: "memory")

// ---------------- projection tile into smem: sT[m][j] = X[m]·W[j] + b[j] ----
__device__ void proj_tile_smem(const float* __restrict__ X, const float* __restrict__ W,
                               const float* __restrict__ bias,
                               float (*sT)[68], int m0, int j0) {
    __shared__ float sX[16][68];   // [k][m]
    __shared__ float sW[16][68];   // [k][j]
    const int tid = threadIdx.x;
    const int tx = tid & 15, ty = tid >> 4;
    const int lrow = tid >> 2, lseg = tid & 3;

    float acc[4][4] = {};
    for (int k0 = 0; k0 < D_MODEL; k0 += 16) {
        float4 xv = *(const float4*)(X + (size_t)(m0 + lrow) * D_MODEL + k0 + lseg * 4);
        float4 wv = *(const float4*)(W + (size_t)(j0 + lrow) * D_MODEL + k0 + lseg * 4);
        sX[lseg * 4 + 0][lrow] = xv.x; sX[lseg * 4 + 1][lrow] = xv.y;
        sX[lseg * 4 + 2][lrow] = xv.z; sX[lseg * 4 + 3][lrow] = xv.w;
        sW[lseg * 4 + 0][lrow] = wv.x; sW[lseg * 4 + 1][lrow] = wv.y;
        sW[lseg * 4 + 2][lrow] = wv.z; sW[lseg * 4 + 3][lrow] = wv.w;
        __syncthreads();
#pragma unroll
        for (int k = 0; k < 16; k++) {
            float4 a = *(const float4*)(&sX[k][ty * 4]);
            float4 b = *(const float4*)(&sW[k][tx * 4]);
            float av[4] = { a.x, a.y, a.z, a.w };
            float bv[4] = { b.x, b.y, b.z, b.w };
#pragma unroll
            for (int i = 0; i < 4; i++)
#pragma unroll
                for (int j = 0; j < 4; j++) acc[i][j] += av[i] * bv[j];
        }
        __syncthreads();
    }
    float4 bv = *(const float4*)(bias + j0 + tx * 4);
    float bb[4] = { bv.x, bv.y, bv.z, bv.w };
#pragma unroll
    for (int i = 0; i < 4; i++)
#pragma unroll
        for (int j = 0; j < 4; j++)
            sT[ty * 4 + i][tx * 4 + j] = acc[i][j] + bb[j];
    __syncthreads();
}

// ---------------- kernel 1: fused prep (wprep + E-proj + P-proj, permuted out) ----
// bid [0,320): wprep  [320,480): E proj tiles  [480,520): P proj tiles
__global__ void __launch_bounds__(256) prep_kernel(
    const float* __restrict__ enc,    const float* __restrict__ pred,
    const float* __restrict__ enc_w,  const float* __restrict__ enc_b,
    const float* __restrict__ pred_w, const float* __restrict__ pred_b,
    const float* __restrict__ out_w,
    float* __restrict__ E, float* __restrict__ Pq, __half* __restrict__ Wt) {
    const int bid = blockIdx.x;
    const int tid = threadIdx.x;
    if (bid < 320) {
        int s = bid * 256 + tid;                  // 16B-slot index, 81920 total
        int lane = s & 31;
        int t1 = s >> 5;
        int ks  = t1 & 1;  t1 >>= 1;
        int nbp = t1 & 15; t1 >>= 4;
        int kt  = t1 % NK;
        int nblk = t1 / NK;
        int g = lane >> 2, tg = lane & 3;
        int v = nblk * 256 + nbp * 16 + g;
        int k = kt * 32 + ks * 16 + 2 * tg;
        const float* w0 = out_w + (size_t)v * JOINT;
        const float* w1 = w0 + (size_t)8 * JOINT;
        float2 aa = *(const float2*)(w0 + k);
        float2 ab = *(const float2*)(w0 + k + 8);
        float2 ba = *(const float2*)(w1 + k);
        float2 bb = *(const float2*)(w1 + k + 8);
        __half2 h0 = __floats2half2_rn(aa.x, aa.y);
        __half2 h1 = __floats2half2_rn(ab.x, ab.y);
        __half2 h2 = __floats2half2_rn(ba.x, ba.y);
        __half2 h3 = __floats2half2_rn(bb.x, bb.y);
        uint4 o;
        o.x = *(const uint32_t*)&h0; o.y = *(const uint32_t*)&h1;
        o.z = *(const uint32_t*)&h2; o.w = *(const uint32_t*)&h3;
        *(uint4*)(Wt + (size_t)s * 8) = o;
    } else if (bid < 480) {
        __shared__ float sT[64][68];
        int idx = bid - 320;                      // 160 tiles: 16 m x 10 j
        int m0 = (idx / 10) * 64, j0 = (idx % 10) * 64;
        proj_tile_smem(enc, enc_w, enc_b, sT, m0, j0);
        // E_perm write: 1024 slots, 4 per thread
#pragma unroll
        for (int i = 0; i < 4; i++) {
            int sid = tid + 256 * i;
            int row = sid >> 4;
            int sl  = sid & 15;
            int kt_l = sl >> 3, ks = (sl >> 2) & 1, tg = sl & 3;
            int col = kt_l * 32 + ks * 16 + 2 * tg;
            float4 v;
            v.x = sT[row][col];     v.y = sT[row][col + 1];
            v.z = sT[row][col + 8]; v.w = sT[row][col + 9];
            *(float4*)(E + (size_t)(m0 + row) * JOINT + j0 + kt_l * 32
                         + (ks * 4 + tg) * 4) = v;
        }
    } else {
        __shared__ float sT[64][68];
        int idx = bid - 480;                      // 40 tiles: 4 b x 10 j
        int b  = idx / 10;
        int j0 = (idx % 10) * 64;
        proj_tile_smem(pred, pred_w, pred_b, sT, b * 64, j0);
        // P_perm write: 1024 slots, 4 per thread
#pragma unroll
        for (int i = 0; i < 4; i++) {
            int sid = tid + 256 * i;
            int kt_l = sid >> 9;
            int pidx = sid & 511;
            int part = pidx >> 8;
            int ptid = pidx & 255;
            int blk = ptid >> 5;
            int rb = blk >> 1, ks = blk & 1;
            int g = (ptid >> 2) & 7, tg = ptid & 3;
            int u = rb * 16 + g + part * 8;
            int col = kt_l * 32 + ks * 16 + 2 * tg;
            float4 v;
            v.x = sT[u][col];     v.y = sT[u][col + 1];
            v.z = sT[u][col + 8]; v.w = sT[u][col + 9];
            *(float4*)(Pq + ((size_t)(b * NK + (j0 >> 5) + kt_l) * 512 + pidx) * 4) = v;
        }
    }
}

// ---------------- kernel 2: fused tanh-join + fp16 mma.sync GEMM ----------------
// smem: A0[0,4K) A1[4K,8K) B0[8K,24K) B1[24K,40K)
// A stage: slot ((rb*2+ks)*32+lane) 16B = {a0,a1,a2,a3}
// B stage: slot ((nbp*2+ks)*32+lane) 16B = {nb_even b0,b1, nb_odd b0,b1}
#define SM_A0 0
#define SM_A1 4096
#define SM_B0 8192
#define SM_B1 24576
#define SM_TOTAL 40960

__global__ void __launch_bounds__(256, 2) gemm_fused_kernel(
    const float* __restrict__ E, const float* __restrict__ P,
    const __half* __restrict__ Wt, const float* __restrict__ out_b,
    float* __restrict__ out) {

    extern __shared__ char smem[];
    uint32_t* const aS[2] = { (uint32_t*)(smem + SM_A0), (uint32_t*)(smem + SM_A1) };
    uint32_t* const bS[2] = { (uint32_t*)(smem + SM_B0), (uint32_t*)(smem + SM_B1) };

    const int tid  = threadIdx.x;
    const int warp = tid >> 5;
    const int lane = tid & 31;
    const int wm = warp >> 2;       // 0..1 : 32-row slab
    const int wn = warp & 3;        // 0..3 : 64-col slab

    const int bt    = blockIdx.y;                 // = b*T + t  (0..1023)
    const int m_blk = bt * BM;
    const int nblk  = blockIdx.x;                 // 0..3 (256-col block)
    const __half* wsrc = Wt + (size_t)nblk * NK * 8192;

    // ---- producer: permuted-load pointers (thread tid <-> A slot tid) ----
    const int ks_p  = (tid >> 5) & 1;
    const int tg_p  = tid & 3;
    const int b_    = bt >> 8;                    // batch
    const float* gEp  = E + (size_t)bt * JOINT + (ks_p * 4 + tg_p) * 4;
    const float* gP0p = P + ((size_t)(b_ * NK) * 512 + tid) * 4;   // +kt*2048

    // ---- B chunk: one contiguous 16KB cp.async copy ----
    auto loadB = [&](int kt, int s) {
        const __half* src = wsrc + (size_t)kt * 8192;
        char* dst = (char*)bS[s];
#pragma unroll
        for (int i = 0; i < 4; i++) {
            int seg = tid + i * 256;
            cp_async16(dst + seg * 16, src + seg * 8);
        }
        CP_COMMIT();
    };

    // ---- produce A chunk 0 (prologue) ----
    {
        float4 eV  = *(const float4*)(gEp);
        float4 p0V = *(const float4*)(gP0p);
        float4 p1V = *(const float4*)(gP0p + 1024);
        __half2 a0 = __floats2half2_rn(tanh_fast(eV.x + p0V.x), tanh_fast(eV.y + p0V.y));
        __half2 a1 = __floats2half2_rn(tanh_fast(eV.x + p1V.x), tanh_fast(eV.y + p1V.y));
        __half2 a2 = __floats2half2_rn(tanh_fast(eV.z + p0V.z), tanh_fast(eV.w + p0V.w));
        __half2 a3 = __floats2half2_rn(tanh_fast(eV.z + p1V.z), tanh_fast(eV.w + p1V.w));
        uint4 st;
        st.x = *(const uint32_t*)&a0; st.y = *(const uint32_t*)&a1;
        st.z = *(const uint32_t*)&a2; st.w = *(const uint32_t*)&a3;
        *(uint4*)(aS[0] + tid * 4) = st;
    }
    loadB(0, 0);

    float c[2][8][4];
#pragma unroll
    for (int mt = 0; mt < 2; mt++)
#pragma unroll
        for (int nt = 0; nt < 8; nt++)
#pragma unroll
            for (int qq = 0; qq < 4; qq++) c[mt][nt][qq] = 0.0f;

    for (int kt = 0; kt < NK; kt++) {
        const int s = kt & 1;
        CP_WAIT0();
        __syncthreads();
        const bool more = (kt + 1 < NK);
        if (more) loadB(kt + 1, s ^ 1);

        // early coalesced LDG.128s for next A chunk (hidden under ks0 MMAs)
        float4 eV, p0V, p1V;
        if (more) {
            eV  = *(const float4*)(gEp  + (size_t)(kt + 1) * 32);
            p0V = *(const float4*)(gP0p + (size_t)(kt + 1) * 2048);
            p1V = *(const float4*)(gP0p + (size_t)(kt + 1) * 2048 + 1024);
        }

        const uint32_t* A  = aS[s];
        const uint32_t* Bs = bS[s];

        // ---------- ks = 0 ----------
        {
            uint32_t a[2][4];
#pragma unroll
            for (int mt = 0; mt < 2; mt++) {
                int rb = wm * 2 + mt;
                uint4 av = *(const uint4*)(A + ((rb * 2 + 0) * 32 + lane) * 4);
                a[mt][0] = av.x; a[mt][1] = av.y; a[mt][2] = av.z; a[mt][3] = av.w;
            }
            uint32_t bf[8][2];
#pragma unroll
            for (int np = 0; np < 4; np++) {
                uint4 bv = *(const uint4*)(Bs + (((wn * 4 + np) * 2 + 0) * 32 + lane) * 4);
                bf[2 * np][0] = bv.x;     bf[2 * np][1] = bv.y;
                bf[2 * np + 1][0] = bv.z; bf[2 * np + 1][1] = bv.w;
            }
#pragma unroll
            for (int mt = 0; mt < 2; mt++)
#pragma unroll
                for (int nt = 0; nt < 8; nt++) {
                    asm volatile(
                        "mma.sync.aligned.m16n8k16.row.col.f32.f16.f16.f32 "
                        "{%0,%1,%2,%3}, {%4,%5,%6,%7}, {%8,%9}, {%0,%1,%2,%3};\n"
                        : "+f"(c[mt][nt][0]), "+f"(c[mt][nt][1]),
                          "+f"(c[mt][nt][2]), "+f"(c[mt][nt][3])
                        : "r"(a[mt][0]), "r"(a[mt][1]), "r"(a[mt][2]), "r"(a[mt][3]),
                          "r"(bf[nt][0]), "r"(bf[nt][1]));
                }
        }

        // ---------- tanh + STS for chunk kt+1 (mid-chunk, overlaps pipes) ----------
        if (more) {
            __half2 a0 = __floats2half2_rn(tanh_fast(eV.x + p0V.x), tanh_fast(eV.y + p0V.y));
            __half2 a1 = __floats2half2_rn(tanh_fast(eV.x + p1V.x), tanh_fast(eV.y + p1V.y));
            __half2 a2 = __floats2half2_rn(tanh_fast(eV.z + p0V.z), tanh_fast(eV.w + p0V.w));
            __half2 a3 = __floats2half2_rn(tanh_fast(eV.z + p1V.z), tanh_fast(eV.w + p1V.w));
            uint4 st;
            st.x = *(const uint32_t*)&a0; st.y = *(const uint32_t*)&a1;
            st.z = *(const uint32_t*)&a2; st.w = *(const uint32_t*)&a3;
            *(uint4*)(aS[s ^ 1] + tid * 4) = st;
        }

        // ---------- ks = 1 ----------
        {
            uint32_t a[2][4];
#pragma unroll
            for (int mt = 0; mt < 2; mt++) {
                int rb = wm * 2 + mt;
                uint4 av = *(const uint4*)(A + ((rb * 2 + 1) * 32 + lane) * 4);
                a[mt][0] = av.x; a[mt][1] = av.y; a[mt][2] = av.z; a[mt][3] = av.w;
            }
            uint32_t bf[8][2];
#pragma unroll
            for (int np = 0; np < 4; np++) {
                uint4 bv = *(const uint4*)(Bs + (((wn * 4 + np) * 2 + 1) * 32 + lane) * 4);
                bf[2 * np][0] = bv.x;     bf[2 * np][1] = bv.y;
                bf[2 * np + 1][0] = bv.z; bf[2 * np + 1][1] = bv.w;
            }
#pragma unroll
            for (int mt = 0; mt < 2; mt++)
#pragma unroll
                for (int nt = 0; nt < 8; nt++) {
                    asm volatile(
                        "mma.sync.aligned.m16n8k16.row.col.f32.f16.f16.f32 "
                        "{%0,%1,%2,%3}, {%4,%5,%6,%7}, {%8,%9}, {%0,%1,%2,%3};\n"
                        : "+f"(c[mt][nt][0]), "+f"(c[mt][nt][1]),
                          "+f"(c[mt][nt][2]), "+f"(c[mt][nt][3])
                        : "r"(a[mt][0]), "r"(a[mt][1]), "r"(a[mt][2]), "r"(a[mt][3]),
                          "r"(bf[nt][0]), "r"(bf[nt][1]));
                }
        }
    }

    // ---- epilogue: +bias, fp32 store ----
    const int m_base = m_blk + wm * 32;
    const int n_base = nblk * BN + wn * 64;
#pragma unroll
    for (int mt = 0; mt < 2; mt++) {
        int row0 = m_base + mt * 16 + (lane >> 2);
#pragma unroll
        for (int nt = 0; nt < 8; nt++) {
            int col0 = n_base + nt * 8 + 2 * (lane & 3);
            float b0 = out_b[col0], b1 = out_b[col0 + 1];
            float2 v0 = make_float2(c[mt][nt][0] + b0, c[mt][nt][1] + b1);
            float2 v1 = make_float2(c[mt][nt][2] + b0, c[mt][nt][3] + b1);
            *(float2*)(out + (size_t)row0 * VOCAB + col0)       = v0;
            *(float2*)(out + (size_t)(row0 + 8) * VOCAB + col0) = v1;
        }
    }
}

// ---------------- launcher ----------------
extern "C" void kernel_launch(void* const* d_in, const int* in_sizes, int n_in,
                              void* d_out, int out_size) {
    const float* enc    = (const float*)d_in[0];
    const float* pred   = (const float*)d_in[1];
    const float* enc_w  = (const float*)d_in[2];
    const float* enc_b  = (const float*)d_in[3];
    const float* pred_w = (const float*)d_in[4];
    const float* pred_b = (const float*)d_in[5];
    const float* out_w  = (const float*)d_in[6];
    const float* out_b  = (const float*)d_in[7];
    float* out = (float*)d_out;

    float *E, *P;
    __half* Wt;
    cudaGetSymbolAddress((void**)&E,  g_E);
    cudaGetSymbolAddress((void**)&P,  g_P);
    cudaGetSymbolAddress((void**)&Wt, g_Wt);

    // fused prep: wprep (320) + E proj (160) + P proj (40), permuted outputs
    prep_kernel<<<520, 256>>>(enc, pred, enc_w, enc_b, pred_w, pred_b, out_w,
                              E, P, Wt);

    // fused tanh-join + GEMM
    cudaFuncSetAttribute(gemm_fused_kernel,
                         cudaFuncAttributeMaxDynamicSharedMemorySize, SM_TOTAL);
    dim3 grd(VOCAB / BN, M_TOTAL / BM);   // (4, 1024)
    gemm_fused_kernel<<<grd, 256, SM_TOTAL>>>(E, P, Wt, out_b, out);
}

// round 11
// speedup vs baseline: 3.0993x; 1.1648x over previous
#include <cuda_runtime.h>
#include <cuda_fp16.h>
#include <cstdint>

#define D_MODEL 512
#define JOINT   640
#define VOCAB   1024
#define BB      4
#define TT      256
#define UU      64
#define M_TOTAL (BB*TT*UU)   // 65536

#define BM 64
#define BN 256
#define BK 32
#define NK (JOINT/BK)        // 20

// ---------------- scratch (no allocations allowed) ----------------
// E_perm / P_perm: permuted fp32 projections (same layout as round 10)
__device__ float  g_E[BB*TT*JOINT];
__device__ float  g_P[BB*UU*JOINT];
// Wt: fp16 out_w in m16n8k16 paired-B fragment order (round-10 layout):
//   16B slot ((((nblk*NK+kt)*16+nbp)*2+ks)*32+lane)
__device__ __half g_Wt[VOCAB*JOINT];
// Zf: fp16 tanh(E+P) in A-fragment order:
//   16B slot ((bt*NK+kt)*256 + ptid), ptid encodes (rb,ks,g,tg) as producer tid
__device__ __half g_Zf[(size_t)M_TOTAL*JOINT];

// ---------------- helpers ----------------
__device__ __forceinline__ float tanh_fast(float x) {
    float y;
    asm("tanh.approx.f32 %0, %1;" : "=f"(y) : "f"(x));
    return y;
}

// ---------------- projection tile into smem: sT[m][j] = X[m]·W[j] + b[j] ----
__device__ void proj_tile_smem(const float* __restrict__ X, const float* __restrict__ W,
                               const float* __restrict__ bias,
                               float (*sT)[68], int m0, int j0) {
    __shared__ float sX[16][68];   // [k][m]
    __shared__ float sW[16][68];   // [k][j]
    const int tid = threadIdx.x;
    const int tx = tid & 15, ty = tid >> 4;
    const int lrow = tid >> 2, lseg = tid & 3;

    float acc[4][4] = {};
    for (int k0 = 0; k0 < D_MODEL; k0 += 16) {
        float4 xv = *(const float4*)(X + (size_t)(m0 + lrow) * D_MODEL + k0 + lseg * 4);
        float4 wv = *(const float4*)(W + (size_t)(j0 + lrow) * D_MODEL + k0 + lseg * 4);
        sX[lseg * 4 + 0][lrow] = xv.x; sX[lseg * 4 + 1][lrow] = xv.y;
        sX[lseg * 4 + 2][lrow] = xv.z; sX[lseg * 4 + 3][lrow] = xv.w;
        sW[lseg * 4 + 0][lrow] = wv.x; sW[lseg * 4 + 1][lrow] = wv.y;
        sW[lseg * 4 + 2][lrow] = wv.z; sW[lseg * 4 + 3][lrow] = wv.w;
        __syncthreads();
#pragma unroll
        for (int k = 0; k < 16; k++) {
            float4 a = *(const float4*)(&sX[k][ty * 4]);
            float4 b = *(const float4*)(&sW[k][tx * 4]);
            float av[4] = { a.x, a.y, a.z, a.w };
            float bv[4] = { b.x, b.y, b.z, b.w };
#pragma unroll
            for (int i = 0; i < 4; i++)
#pragma unroll
                for (int j = 0; j < 4; j++) acc[i][j] += av[i] * bv[j];
        }
        __syncthreads();
    }
    float4 bv = *(const float4*)(bias + j0 + tx * 4);
    float bb[4] = { bv.x, bv.y, bv.z, bv.w };
#pragma unroll
    for (int i = 0; i < 4; i++)
#pragma unroll
        for (int j = 0; j < 4; j++)
            sT[ty * 4 + i][tx * 4 + j] = acc[i][j] + bb[j];
    __syncthreads();
}

// ---------------- kernel 1: fused prep (wprep + E-proj + P-proj, permuted out) ----
// bid [0,320): wprep  [320,480): E proj tiles  [480,520): P proj tiles
__global__ void __launch_bounds__(256) prep_kernel(
    const float* __restrict__ enc,    const float* __restrict__ pred,
    const float* __restrict__ enc_w,  const float* __restrict__ enc_b,
    const float* __restrict__ pred_w, const float* __restrict__ pred_b,
    const float* __restrict__ out_w,
    float* __restrict__ E, float* __restrict__ Pq, __half* __restrict__ Wt) {
    const int bid = blockIdx.x;
    const int tid = threadIdx.x;
    if (bid < 320) {
        int s = bid * 256 + tid;                  // 16B-slot index, 81920 total
        int lane = s & 31;
        int t1 = s >> 5;
        int ks  = t1 & 1;  t1 >>= 1;
        int nbp = t1 & 15; t1 >>= 4;
        int kt  = t1 % NK;
        int nblk = t1 / NK;
        int g = lane >> 2, tg = lane & 3;
        int v = nblk * 256 + nbp * 16 + g;
        int k = kt * 32 + ks * 16 + 2 * tg;
        const float* w0 = out_w + (size_t)v * JOINT;
        const float* w1 = w0 + (size_t)8 * JOINT;
        float2 aa = *(const float2*)(w0 + k);
        float2 ab = *(const float2*)(w0 + k + 8);
        float2 ba = *(const float2*)(w1 + k);
        float2 bb = *(const float2*)(w1 + k + 8);
        __half2 h0 = __floats2half2_rn(aa.x, aa.y);
        __half2 h1 = __floats2half2_rn(ab.x, ab.y);
        __half2 h2 = __floats2half2_rn(ba.x, ba.y);
        __half2 h3 = __floats2half2_rn(bb.x, bb.y);
        uint4 o;
        o.x = *(const uint32_t*)&h0; o.y = *(const uint32_t*)&h1;
        o.z = *(const uint32_t*)&h2; o.w = *(const uint32_t*)&h3;
        *(uint4*)(Wt + (size_t)s * 8) = o;
    } else if (bid < 480) {
        __shared__ float sT[64][68];
        int idx = bid - 320;                      // 160 tiles: 16 m x 10 j
        int m0 = (idx / 10) * 64, j0 = (idx % 10) * 64;
        proj_tile_smem(enc, enc_w, enc_b, sT, m0, j0);
#pragma unroll
        for (int i = 0; i < 4; i++) {
            int sid = tid + 256 * i;
            int row = sid >> 4;
            int sl  = sid & 15;
            int kt_l = sl >> 3, ks = (sl >> 2) & 1, tg = sl & 3;
            int col = kt_l * 32 + ks * 16 + 2 * tg;
            float4 v;
            v.x = sT[row][col];     v.y = sT[row][col + 1];
            v.z = sT[row][col + 8]; v.w = sT[row][col + 9];
            *(float4*)(E + (size_t)(m0 + row) * JOINT + j0 + kt_l * 32
                         + (ks * 4 + tg) * 4) = v;
        }
    } else {
        __shared__ float sT[64][68];
        int idx = bid - 480;                      // 40 tiles: 4 b x 10 j
        int b  = idx / 10;
        int j0 = (idx % 10) * 64;
        proj_tile_smem(pred, pred_w, pred_b, sT, b * 64, j0);
#pragma unroll
        for (int i = 0; i < 4; i++) {
            int sid = tid + 256 * i;
            int kt_l = sid >> 9;
            int pidx = sid & 511;
            int part = pidx >> 8;
            int ptid = pidx & 255;
            int blk = ptid >> 5;
            int rb = blk >> 1, ks = blk & 1;
            int g = (ptid >> 2) & 7, tg = ptid & 3;
            int u = rb * 16 + g + part * 8;
            int col = kt_l * 32 + ks * 16 + 2 * tg;
            float4 v;
            v.x = sT[u][col];     v.y = sT[u][col + 1];
            v.z = sT[u][col + 8]; v.w = sT[u][col + 9];
            *(float4*)(Pq + ((size_t)(b * NK + (j0 >> 5) + kt_l) * 512 + pidx) * 4) = v;
        }
    }
}

// ---------------- kernel 2: zgen — Zf = fp16(tanh(E+P)) in A-fragment order ----
// block = one bt (1024 blocks), thread tid = producer slot, loop over kt.
__global__ void __launch_bounds__(256) zgen_kernel(
    const float* __restrict__ E, const float* __restrict__ P,
    __half* __restrict__ Zf) {
    const int tid = threadIdx.x;
    const int bt  = blockIdx.x;
    const int b_  = bt >> 8;
    const int ks_p = (tid >> 5) & 1;
    const int tg_p = tid & 3;
    const float* gEp  = E + (size_t)bt * JOINT + (ks_p * 4 + tg_p) * 4;
    const float* gP0p = P + ((size_t)(b_ * NK) * 512 + tid) * 4;
    uint4* dst = (uint4*)Zf + (size_t)bt * NK * 256 + tid;

#pragma unroll 4
    for (int kt = 0; kt < NK; kt++) {
        float4 eV  = *(const float4*)(gEp  + (size_t)kt * 32);
        float4 p0V = *(const float4*)(gP0p + (size_t)kt * 2048);
        float4 p1V = *(const float4*)(gP0p + (size_t)kt * 2048 + 1024);
        __half2 a0 = __floats2half2_rn(tanh_fast(eV.x + p0V.x), tanh_fast(eV.y + p0V.y));
        __half2 a1 = __floats2half2_rn(tanh_fast(eV.x + p1V.x), tanh_fast(eV.y + p1V.y));
        __half2 a2 = __floats2half2_rn(tanh_fast(eV.z + p0V.z), tanh_fast(eV.w + p0V.w));
        __half2 a3 = __floats2half2_rn(tanh_fast(eV.z + p1V.z), tanh_fast(eV.w + p1V.w));
        uint4 st;
        st.x = *(const uint32_t*)&a0; st.y = *(const uint32_t*)&a1;
        st.z = *(const uint32_t*)&a2; st.w = *(const uint32_t*)&a3;
        dst[kt * 256] = st;
    }
}

// ---------------- kernel 3: barrier-free register-streamed fp16 GEMM ----------
// A fragments: Zf slot (bt*NK+kt)*256 + ((wm*2+mt)*2+ks)*32 + lane
// B fragments: Wt slot (nblk*NK+kt)*1024 + ((wn*4+np)*2+ks)*32 + lane
//   (uint4 = {nb_even b0,b1, nb_odd b0,b1})
__global__ void __launch_bounds__(256, 2) gemm_kernel(
    const __half* __restrict__ Zf, const __half* __restrict__ Wt,
    const float* __restrict__ out_b, float* __restrict__ out) {

    const int tid  = threadIdx.x;
    const int warp = tid >> 5;
    const int lane = tid & 31;
    const int wm = warp >> 2;       // 0..1 : 32-row slab
    const int wn = warp & 3;        // 0..3 : 64-col slab

    const int bt    = blockIdx.y;   // 0..1023
    const int nblk  = blockIdx.x;   // 0..3

    const uint4* Abase = (const uint4*)Zf + (size_t)bt * NK * 256
                         + (size_t)(wm * 2) * 64 + lane;       // +mt*128? see ldA
    const uint4* Bbase = (const uint4*)Wt + (size_t)nblk * NK * 1024
                         + (size_t)(wn * 4) * 64 + lane;

    // slot strides: A: mt -> +2*32, ks -> +32, kt -> +256
    //               B: np -> +2*32, ks -> +32, kt -> +1024
    auto ldA = [&](int kt, int mt, int ks) -> uint4 {
        return Abase[(size_t)kt * 256 + mt * 64 + ks * 32];
    };
    auto ldB = [&](int kt, int np, int ks) -> uint4 {
        return Bbase[(size_t)kt * 1024 + np * 64 + ks * 32];
    };

    float c[2][8][4];
#pragma unroll
    for (int mt = 0; mt < 2; mt++)
#pragma unroll
        for (int nt = 0; nt < 8; nt++)
#pragma unroll
            for (int qq = 0; qq < 4; qq++) c[mt][nt][qq] = 0.0f;

    uint4 aC[2], bC[4], aN[2], bN[4];
#pragma unroll
    for (int mt = 0; mt < 2; mt++) aC[mt] = ldA(0, mt, 0);
#pragma unroll
    for (int np = 0; np < 4; np++) bC[np] = ldB(0, np, 0);

    auto domma = [&](const uint4* a4, const uint4* b4) {
#pragma unroll
        for (int mt = 0; mt < 2; mt++) {
            uint32_t a[4] = { a4[mt].x, a4[mt].y, a4[mt].z, a4[mt].w };
#pragma unroll
            for (int np = 0; np < 4; np++) {
                uint32_t b0[2] = { b4[np].x, b4[np].y };
                uint32_t b1[2] = { b4[np].z, b4[np].w };
                asm volatile(
                    "mma.sync.aligned.m16n8k16.row.col.f32.f16.f16.f32 "
                    "{%0,%1,%2,%3}, {%4,%5,%6,%7}, {%8,%9}, {%0,%1,%2,%3};\n"
                    : "+f"(c[mt][2 * np][0]), "+f"(c[mt][2 * np][1]),
                      "+f"(c[mt][2 * np][2]), "+f"(c[mt][2 * np][3])
                    : "r"(a[0]), "r"(a[1]), "r"(a[2]), "r"(a[3]),
                      "r"(b0[0]), "r"(b0[1]));
                asm volatile(
                    "mma.sync.aligned.m16n8k16.row.col.f32.f16.f16.f32 "
                    "{%0,%1,%2,%3}, {%4,%5,%6,%7}, {%8,%9}, {%0,%1,%2,%3};\n"
                    : "+f"(c[mt][2 * np + 1][0]), "+f"(c[mt][2 * np + 1][1]),
                      "+f"(c[mt][2 * np + 1][2]), "+f"(c[mt][2 * np + 1][3])
                    : "r"(a[0]), "r"(a[1]), "r"(a[2]), "r"(a[3]),
                      "r"(b1[0]), "r"(b1[1]));
            }
        }
    };

    for (int kt = 0; kt < NK; kt++) {
        // prefetch ks=1 of this chunk
#pragma unroll
        for (int mt = 0; mt < 2; mt++) aN[mt] = ldA(kt, mt, 1);
#pragma unroll
        for (int np = 0; np < 4; np++) bN[np] = ldB(kt, np, 1);

        domma(aC, bC);      // ks = 0

        // prefetch ks=0 of next chunk
        if (kt + 1 < NK) {
#pragma unroll
            for (int mt = 0; mt < 2; mt++) aC[mt] = ldA(kt + 1, mt, 0);
#pragma unroll
            for (int np = 0; np < 4; np++) bC[np] = ldB(kt + 1, np, 0);
        }

        domma(aN, bN);      // ks = 1
    }

    // ---- epilogue: +bias, fp32 store ----
    const int m_base = bt * BM + wm * 32;
    const int n_base = nblk * BN + wn * 64;
#pragma unroll
    for (int mt = 0; mt < 2; mt++) {
        int row0 = m_base + mt * 16 + (lane >> 2);
#pragma unroll
        for (int nt = 0; nt < 8; nt++) {
            int col0 = n_base + nt * 8 + 2 * (lane & 3);
            float b0 = out_b[col0], b1 = out_b[col0 + 1];
            float2 v0 = make_float2(c[mt][nt][0] + b0, c[mt][nt][1] + b1);
            float2 v1 = make_float2(c[mt][nt][2] + b0, c[mt][nt][3] + b1);
            *(float2*)(out + (size_t)row0 * VOCAB + col0)       = v0;
            *(float2*)(out + (size_t)(row0 + 8) * VOCAB + col0) = v1;
        }
    }
}

// ---------------- launcher ----------------
extern "C" void kernel_launch(void* const* d_in, const int* in_sizes, int n_in,
                              void* d_out, int out_size) {
    const float* enc    = (const float*)d_in[0];
    const float* pred   = (const float*)d_in[1];
    const float* enc_w  = (const float*)d_in[2];
    const float* enc_b  = (const float*)d_in[3];
    const float* pred_w = (const float*)d_in[4];
    const float* pred_b = (const float*)d_in[5];
    const float* out_w  = (const float*)d_in[6];
    const float* out_b  = (const float*)d_in[7];
    float* out = (float*)d_out;

    float *E, *P;
    __half *Wt, *Zf;
    cudaGetSymbolAddress((void**)&E,  g_E);
    cudaGetSymbolAddress((void**)&P,  g_P);
    cudaGetSymbolAddress((void**)&Wt, g_Wt);
    cudaGetSymbolAddress((void**)&Zf, g_Zf);

    // fused prep: wprep (320) + E proj (160) + P proj (40), permuted outputs
    prep_kernel<<<520, 256>>>(enc, pred, enc_w, enc_b, pred_w, pred_b, out_w,
                              E, P, Wt);
    // Zf = fp16 tanh(E+P) in fragment order (tanh computed once, not 4x)
    zgen_kernel<<<M_TOTAL / BM, 256>>>(E, P, Zf);
    // barrier-free register-streamed GEMM
    dim3 grd(VOCAB / BN, M_TOTAL / BM);   // (4, 1024)
    gemm_kernel<<<grd, 256>>>(Zf, Wt, out_b, out);
}

// round 12
// speedup vs baseline: 3.1341x; 1.0112x over previous
#include <cuda_runtime.h>
#include <cuda_fp16.h>
#include <cstdint>

#define D_MODEL 512
#define JOINT   640
#define VOCAB   1024
#define BB      4
#define TT      256
#define UU      64
#define M_TOTAL (BB*TT*UU)   // 65536

#define BM 64
#define BN 256
#define BK 32
#define NK (JOINT/BK)        // 20

// ---------------- scratch (no allocations allowed) ----------------
__device__ float  g_E[BB*TT*JOINT];       // permuted fp32 E projection
__device__ float  g_P[BB*UU*JOINT];       // permuted fp32 P projection
// Wt: fp16 out_w, m16n8k16 paired-B fragment order (round-10/11 layout)
__device__ __half g_Wt[VOCAB*JOINT];
// Zf: fp16 tanh(E+P), A-fragment order (round-11 layout)
__device__ __half g_Zf[(size_t)M_TOTAL*JOINT];

// ---------------- helpers ----------------
__device__ __forceinline__ float tanh_fast(float x) {
    float y;
    asm("tanh.approx.f32 %0, %1;" : "=f"(y) : "f"(x));
    return y;
}
__device__ __forceinline__ uint32_t smem_u32(const void* p) {
    return (uint32_t)__cvta_generic_to_shared(p);
}
__device__ __forceinline__ void cp_async16(void* smem_dst, const void* gmem_src) {
    asm volatile("cp.async.cg.shared.global [%0], [%1], 16;\n"
                 :: "r"(smem_u32(smem_dst)), "l"(gmem_src));
}
#define CP_COMMIT() asm volatile("cp.async.commit_group;\n" ::: "memory")
#define CP_WAIT0()  asm volatile("cp.async.wait_group 0;\n" ::: "memory")
#define CP_WAIT1()  asm volatile("cp.async.wait_group 1;\n" ::: "memory")

// ---------------- kernel 1: fused prep (wprep + E-proj + P-proj) --------------
// Projection: 64x64 tile, thread (tx,ty) owns rows ty*4+i and permuted cols
// {base, base+1, base+8, base+9}, base = (tx>>2)*16 + (tx&3)*2  ->  outputs are
// written directly in the permuted fragment layout, no staging buffer.
// bid [0,320): wprep  [320,480): E proj tiles  [480,520): P proj tiles
__global__ void __launch_bounds__(256) prep_kernel(
    const float* __restrict__ enc,    const float* __restrict__ pred,
    const float* __restrict__ enc_w,  const float* __restrict__ enc_b,
    const float* __restrict__ pred_w, const float* __restrict__ pred_b,
    const float* __restrict__ out_w,
    float* __restrict__ E, float* __restrict__ Pq, __half* __restrict__ Wt) {
    const int bid = blockIdx.x;
    const int tid = threadIdx.x;

    if (bid < 320) {
        int s = bid * 256 + tid;                  // 16B-slot index, 81920 total
        int lane = s & 31;
        int t1 = s >> 5;
        int ks  = t1 & 1;  t1 >>= 1;
        int nbp = t1 & 15; t1 >>= 4;
        int kt  = t1 % NK;
        int nblk = t1 / NK;
        int g = lane >> 2, tg = lane & 3;
        int v = nblk * 256 + nbp * 16 + g;
        int k = kt * 32 + ks * 16 + 2 * tg;
        const float* w0 = out_w + (size_t)v * JOINT;
        const float* w1 = w0 + (size_t)8 * JOINT;
        float2 aa = *(const float2*)(w0 + k);
        float2 ab = *(const float2*)(w0 + k + 8);
        float2 ba = *(const float2*)(w1 + k);
        float2 bb = *(const float2*)(w1 + k + 8);
        __half2 h0 = __floats2half2_rn(aa.x, aa.y);
        __half2 h1 = __floats2half2_rn(ab.x, ab.y);
        __half2 h2 = __floats2half2_rn(ba.x, ba.y);
        __half2 h3 = __floats2half2_rn(bb.x, bb.y);
        uint4 o;
        o.x = *(const uint32_t*)&h0; o.y = *(const uint32_t*)&h1;
        o.z = *(const uint32_t*)&h2; o.w = *(const uint32_t*)&h3;
        *(uint4*)(Wt + (size_t)s * 8) = o;
        return;
    }

    // ---- projection branches ----
    __shared__ float sX[2][16][68];   // [buf][k][m]
    __shared__ float sW[2][16][68];   // [buf][k][j]
    const bool isE = (bid < 480);
    const int idx = isE ? (bid - 320) : (bid - 480);
    const int m0 = (idx / 10) * 64;
    const int j0 = (idx % 10) * 64;
    const float* X  = isE ? enc    : pred;
    const float* W  = isE ? enc_w  : pred_w;
    const float* Bi = isE ? enc_b  : pred_b;

    const int tx = tid & 15, ty = tid >> 4;
    const int lrow = tid >> 2, lseg = tid & 3;
    const int base = (tx >> 2) * 16 + (tx & 3) * 2;   // permuted col base
    const int kt_l = (tx >> 2) >> 1;
    const int ksq  = (tx >> 2) & 1;
    const int tg   = tx & 3;

    const float* Xr = X + (size_t)(m0 + lrow) * D_MODEL + lseg * 4;
    const float* Wr = W + (size_t)(j0 + lrow) * D_MODEL + lseg * 4;

    // prologue: tile 0 into buf 0
    {
        float4 xv = *(const float4*)(Xr);
        float4 wv = *(const float4*)(Wr);
        sX[0][lseg * 4 + 0][lrow] = xv.x; sX[0][lseg * 4 + 1][lrow] = xv.y;
        sX[0][lseg * 4 + 2][lrow] = xv.z; sX[0][lseg * 4 + 3][lrow] = xv.w;
        sW[0][lseg * 4 + 0][lrow] = wv.x; sW[0][lseg * 4 + 1][lrow] = wv.y;
        sW[0][lseg * 4 + 2][lrow] = wv.z; sW[0][lseg * 4 + 3][lrow] = wv.w;
    }
    __syncthreads();

    float acc[4][4] = {};
    for (int it = 0; it < 32; it++) {
        const int cur = it & 1;
        float4 xv, wv;
        const bool more = (it < 31);
        if (more) {
            xv = *(const float4*)(Xr + (it + 1) * 16);
            wv = *(const float4*)(Wr + (it + 1) * 16);
        }
#pragma unroll
        for (int k = 0; k < 16; k++) {
            float4 a = *(const float4*)(&sX[cur][k][ty * 4]);
            float2 b01 = *(const float2*)(&sW[cur][k][base]);
            float2 b89 = *(const float2*)(&sW[cur][k][base + 8]);
            float av[4] = { a.x, a.y, a.z, a.w };
#pragma unroll
            for (int i = 0; i < 4; i++) {
                acc[i][0] += av[i] * b01.x;
                acc[i][1] += av[i] * b01.y;
                acc[i][2] += av[i] * b89.x;
                acc[i][3] += av[i] * b89.y;
            }
        }
        if (more) {
            const int nxt = cur ^ 1;
            sX[nxt][lseg * 4 + 0][lrow] = xv.x; sX[nxt][lseg * 4 + 1][lrow] = xv.y;
            sX[nxt][lseg * 4 + 2][lrow] = xv.z; sX[nxt][lseg * 4 + 3][lrow] = xv.w;
            sW[nxt][lseg * 4 + 0][lrow] = wv.x; sW[nxt][lseg * 4 + 1][lrow] = wv.y;
            sW[nxt][lseg * 4 + 2][lrow] = wv.z; sW[nxt][lseg * 4 + 3][lrow] = wv.w;
        }
        __syncthreads();
    }

    float2 bb01 = *(const float2*)(Bi + j0 + base);
    float2 bb89 = *(const float2*)(Bi + j0 + base + 8);
#pragma unroll
    for (int i = 0; i < 4; i++) {
        float4 v;
        v.x = acc[i][0] + bb01.x; v.y = acc[i][1] + bb01.y;
        v.z = acc[i][2] + bb89.x; v.w = acc[i][3] + bb89.y;
        int row = ty * 4 + i;
        if (isE) {
            *(float4*)(E + (size_t)(m0 + row) * JOINT + j0 + kt_l * 32
                         + (ksq * 4 + tg) * 4) = v;
        } else {
            int b  = m0 >> 6;                     // pred tile: 64 rows = all U
            int u  = row;
            int rb = u >> 4, part = (u >> 3) & 1, g = u & 7;
            int ptid = ((rb * 2 + ksq) * 8 + g) * 4 + tg;
            int pidx = part * 256 + ptid;
            int kt = (j0 >> 5) + kt_l;
            *(float4*)(Pq + ((size_t)(b * NK + kt) * 512 + pidx) * 4) = v;
        }
    }
}

// ---------------- kernel 2: zgen — Zf = fp16(tanh(E+P)) in A-fragment order ----
__global__ void __launch_bounds__(256) zgen_kernel(
    const float* __restrict__ E, const float* __restrict__ P,
    __half* __restrict__ Zf) {
    const int tid = threadIdx.x;
    const int bt  = blockIdx.x;
    const int b_  = bt >> 8;
    const int ks_p = (tid >> 5) & 1;
    const int tg_p = tid & 3;
    const float* gEp  = E + (size_t)bt * JOINT + (ks_p * 4 + tg_p) * 4;
    const float* gP0p = P + ((size_t)(b_ * NK) * 512 + tid) * 4;
    uint4* dst = (uint4*)Zf + (size_t)bt * NK * 256 + tid;

#pragma unroll 4
    for (int kt = 0; kt < NK; kt++) {
        float4 eV  = *(const float4*)(gEp  + (size_t)kt * 32);
        float4 p0V = *(const float4*)(gP0p + (size_t)kt * 2048);
        float4 p1V = *(const float4*)(gP0p + (size_t)kt * 2048 + 1024);
        __half2 a0 = __floats2half2_rn(tanh_fast(eV.x + p0V.x), tanh_fast(eV.y + p0V.y));
        __half2 a1 = __floats2half2_rn(tanh_fast(eV.x + p1V.x), tanh_fast(eV.y + p1V.y));
        __half2 a2 = __floats2half2_rn(tanh_fast(eV.z + p0V.z), tanh_fast(eV.w + p0V.w));
        __half2 a3 = __floats2half2_rn(tanh_fast(eV.z + p1V.z), tanh_fast(eV.w + p1V.w));
        uint4 st;
        st.x = *(const uint32_t*)&a0; st.y = *(const uint32_t*)&a1;
        st.z = *(const uint32_t*)&a2; st.w = *(const uint32_t*)&a3;
        dst[kt * 256] = st;
    }
}

// ---------------- kernel 3: barrier-free GEMM, per-warp cp.async staging ------
// smem: [warp][stage 0..1][slot 0..11][lane] uint4 ; slot: A mt*2+ks (0..3),
// B 4+np*2+ks (4..11). Depth-2, wait_group per warp, NO block barriers.
#define DSTAGE 2
#define GEMM_SMEM (8 * DSTAGE * 12 * 32 * 16)   // 98304 bytes

__global__ void __launch_bounds__(256, 2) gemm_kernel(
    const __half* __restrict__ Zf, const __half* __restrict__ Wt,
    const float* __restrict__ out_b, float* __restrict__ out) {

    extern __shared__ uint4 smq[];

    const int tid  = threadIdx.x;
    const int warp = tid >> 5;
    const int lane = tid & 31;
    const int wm = warp >> 2;       // 0..1 : 32-row slab
    const int wn = warp & 3;        // 0..3 : 64-col slab

    const int bt    = blockIdx.y;   // 0..1023
    const int nblk  = blockIdx.x;   // 0..3

    const uint4* Ab = (const uint4*)Zf + (size_t)bt * NK * 256
                      + (size_t)(wm * 2) * 64 + lane;
    const uint4* Bb = (const uint4*)Wt + (size_t)nblk * NK * 1024
                      + (size_t)(wn * 4) * 64 + lane;

    uint4* const ws = smq + (size_t)warp * DSTAGE * 12 * 32 + lane;

    auto issue = [&](int kt, int stage) {
        uint4* dst = ws + stage * (12 * 32);
        const uint4* a = Ab + (size_t)kt * 256;
        const uint4* b = Bb + (size_t)kt * 1024;
        cp_async16(dst + 0 * 32, a);            // mt0 ks0
        cp_async16(dst + 1 * 32, a + 32);       // mt0 ks1
        cp_async16(dst + 2 * 32, a + 64);       // mt1 ks0
        cp_async16(dst + 3 * 32, a + 96);       // mt1 ks1
#pragma unroll
        for (int np = 0; np < 4; np++) {
            cp_async16(dst + (4 + np * 2) * 32, b + np * 64);        // ks0
            cp_async16(dst + (5 + np * 2) * 32, b + np * 64 + 32);   // ks1
        }
        CP_COMMIT();
    };

    float c[2][8][4];
#pragma unroll
    for (int mt = 0; mt < 2; mt++)
#pragma unroll
        for (int nt = 0; nt < 8; nt++)
#pragma unroll
            for (int qq = 0; qq < 4; qq++) c[mt][nt][qq] = 0.0f;

    auto consume = [&](int stage) {
        const uint4* s = ws + stage * (12 * 32);
#pragma unroll
        for (int ks = 0; ks < 2; ks++) {
            uint4 aF[2], bF[4];
#pragma unroll
            for (int mt = 0; mt < 2; mt++) aF[mt] = s[(mt * 2 + ks) * 32];
#pragma unroll
            for (int np = 0; np < 4; np++) bF[np] = s[(4 + np * 2 + ks) * 32];
#pragma unroll
            for (int mt = 0; mt < 2; mt++) {
                uint32_t a[4] = { aF[mt].x, aF[mt].y, aF[mt].z, aF[mt].w };
#pragma unroll
                for (int np = 0; np < 4; np++) {
                    asm volatile(
                        "mma.sync.aligned.m16n8k16.row.col.f32.f16.f16.f32 "
                        "{%0,%1,%2,%3}, {%4,%5,%6,%7}, {%8,%9}, {%0,%1,%2,%3};\n"
                        : "+f"(c[mt][2 * np][0]), "+f"(c[mt][2 * np][1]),
                          "+f"(c[mt][2 * np][2]), "+f"(c[mt][2 * np][3])
                        : "r"(a[0]), "r"(a[1]), "r"(a[2]), "r"(a[3]),
                          "r"(bF[np].x), "r"(bF[np].y));
                    asm volatile(
                        "mma.sync.aligned.m16n8k16.row.col.f32.f16.f16.f32 "
                        "{%0,%1,%2,%3}, {%4,%5,%6,%7}, {%8,%9}, {%0,%1,%2,%3};\n"
                        : "+f"(c[mt][2 * np + 1][0]), "+f"(c[mt][2 * np + 1][1]),
                          "+f"(c[mt][2 * np + 1][2]), "+f"(c[mt][2 * np + 1][3])
                        : "r"(a[0]), "r"(a[1]), "r"(a[2]), "r"(a[3]),
                          "r"(bF[np].z), "r"(bF[np].w));
                }
            }
        }
    };

    issue(0, 0);
    issue(1, 1);

    for (int kt = 0; kt < NK - 1; kt++) {
        CP_WAIT1();                 // group kt retired (per-warp)
        consume(kt & 1);
        if (kt + 2 < NK) issue(kt + 2, kt & 1);   // reuse stage just consumed
    }
    CP_WAIT0();
    consume((NK - 1) & 1);

    // ---- epilogue: +bias, fp32 store ----
    const int m_base = bt * BM + wm * 32;
    const int n_base = nblk * BN + wn * 64;
#pragma unroll
    for (int mt = 0; mt < 2; mt++) {
        int row0 = m_base + mt * 16 + (lane >> 2);
#pragma unroll
        for (int nt = 0; nt < 8; nt++) {
            int col0 = n_base + nt * 8 + 2 * (lane & 3);
            float b0 = out_b[col0], b1 = out_b[col0 + 1];
            float2 v0 = make_float2(c[mt][nt][0] + b0, c[mt][nt][1] + b1);
            float2 v1 = make_float2(c[mt][nt][2] + b0, c[mt][nt][3] + b1);
            *(float2*)(out + (size_t)row0 * VOCAB + col0)       = v0;
            *(float2*)(out + (size_t)(row0 + 8) * VOCAB + col0) = v1;
        }
    }
}

// ---------------- launcher ----------------
extern "C" void kernel_launch(void* const* d_in, const int* in_sizes, int n_in,
                              void* d_out, int out_size) {
    const float* enc    = (const float*)d_in[0];
    const float* pred   = (const float*)d_in[1];
    const float* enc_w  = (const float*)d_in[2];
    const float* enc_b  = (const float*)d_in[3];
    const float* pred_w = (const float*)d_in[4];
    const float* pred_b = (const float*)d_in[5];
    const float* out_w  = (const float*)d_in[6];
    const float* out_b  = (const float*)d_in[7];
    float* out = (float*)d_out;

    float *E, *P;
    __half *Wt, *Zf;
    cudaGetSymbolAddress((void**)&E,  g_E);
    cudaGetSymbolAddress((void**)&P,  g_P);
    cudaGetSymbolAddress((void**)&Wt, g_Wt);
    cudaGetSymbolAddress((void**)&Zf, g_Zf);

    // fused prep: wprep (320) + E proj (160) + P proj (40), permuted outputs
    prep_kernel<<<520, 256>>>(enc, pred, enc_w, enc_b, pred_w, pred_b, out_w,
                              E, P, Wt);
    // Zf = fp16 tanh(E+P) in fragment order
    zgen_kernel<<<M_TOTAL / BM, 256>>>(E, P, Zf);
    // barrier-free GEMM with per-warp cp.async depth-2 pipeline
    cudaFuncSetAttribute(gemm_kernel,
                         cudaFuncAttributeMaxDynamicSharedMemorySize, GEMM_SMEM);
    dim3 grd(VOCAB / BN, M_TOTAL / BM);   // (4, 1024)
    gemm_kernel<<<grd, 256, GEMM_SMEM>>>(Zf, Wt, out_b, out);
}